// round 4
// baseline (speedup 1.0000x reference)
#include <cuda_runtime.h>
#include <cuda_bf16.h>
#include <math.h>

#define N_NODES 40000
#define DIN 512
#define DH 256
#define DOUT 47
#define MAX_E 640000

// Scratch (no cudaMalloc allowed) — __device__ globals.
__device__ __align__(16) float g_h1[N_NODES * DH];   // X @ W1
__device__ __align__(16) float g_o1[N_NODES * DH];   // aggregated layer-1 (pre-relu)
__device__ __align__(16) float g_h2[N_NODES * DOUT]; // relu(o1) @ W2
__device__ __align__(16) float g_o2[N_NODES * DOUT]; // aggregated layer-2
__device__ float g_dis[N_NODES];                     // deg^-1/2 (deg includes self-loop)
__device__ int   g_deg[N_NODES];
__device__ int   g_src[MAX_E];
__device__ int   g_dst[MAX_E];
__device__ int   g_is64;                             // 1 if edge_index is int64

// ---------------------------------------------------------------------------
// Dtype detection: interpret first 2E int32 words. If the underlying buffer is
// int64 (values in [0,40000)), every odd word is a zero high-half. If int32,
// odd words are random src indices — essentially surely non-zero somewhere.
// ---------------------------------------------------------------------------
__global__ void k_detect_init() { g_is64 = 1; }

__global__ void k_detect(const int* __restrict__ w, int nwords2E) {
    int i = blockIdx.x * blockDim.x + threadIdx.x;
    int odd = 2 * i + 1;
    if (odd < nwords2E && w[odd] != 0) g_is64 = 0;
}

// Normalize indices to int32 arrays g_src/g_dst.
__global__ void k_extract(const int* __restrict__ w, int E) {
    int e = blockIdx.x * blockDim.x + threadIdx.x;
    if (e >= E) return;
    if (g_is64) {
        g_src[e] = w[2 * e];             // lo word of src[e]
        g_dst[e] = w[2 * (E + e)];       // lo word of dst[e]
    } else {
        g_src[e] = w[e];
        g_dst[e] = w[E + e];
    }
}

// ---------------------------------------------------------------------------
// Degree / normalization
// ---------------------------------------------------------------------------
__global__ void k_zero_deg() {
    int i = blockIdx.x * blockDim.x + threadIdx.x;
    if (i < N_NODES) g_deg[i] = 0;
}

__global__ void k_count_deg(int E) {
    int i = blockIdx.x * blockDim.x + threadIdx.x;
    if (i < E) atomicAdd(&g_deg[g_dst[i]], 1);
}

__global__ void k_dis() {
    int i = blockIdx.x * blockDim.x + threadIdx.x;
    if (i < N_NODES) g_dis[i] = rsqrtf((float)g_deg[i] + 1.0f);  // +1 = self loop
}

// ---------------------------------------------------------------------------
// GEMM1: h1 = X[40000,512] @ W1[512,256]
// Fused epilogue: o1 = b1 + dis[row]^2 * h1   (self-loop term + bias init)
// 64x64 tile, 256 threads, 4x4 microtile, BK=16.
// ---------------------------------------------------------------------------
#define BK 16
__global__ void __launch_bounds__(256)
k_gemm1(const float* __restrict__ A,   // X
        const float* __restrict__ B,   // W1
        const float* __restrict__ b1) {
    __shared__ float As[64][BK + 4];
    __shared__ float Bs[BK][64];

    const int tid = threadIdx.x;
    const int tx = tid & 15;       // 0..15 -> col group
    const int ty = tid >> 4;       // 0..15 -> row group
    const int bm = blockIdx.y * 64;
    const int bn = blockIdx.x * 64;

    float acc[4][4];
#pragma unroll
    for (int i = 0; i < 4; i++)
#pragma unroll
        for (int j = 0; j < 4; j++) acc[i][j] = 0.0f;

    for (int k0 = 0; k0 < DIN; k0 += BK) {
#pragma unroll
        for (int i = tid; i < 64 * BK; i += 256) {
            int r = i >> 4, c = i & 15;
            As[r][c] = A[(size_t)(bm + r) * DIN + k0 + c];
        }
#pragma unroll
        for (int i = tid; i < BK * 64; i += 256) {
            int r = i >> 6, c = i & 63;
            Bs[r][c] = B[(size_t)(k0 + r) * DH + bn + c];
        }
        __syncthreads();

#pragma unroll
        for (int k = 0; k < BK; k++) {
            float a[4], b[4];
#pragma unroll
            for (int i = 0; i < 4; i++) a[i] = As[ty * 4 + i][k];
#pragma unroll
            for (int j = 0; j < 4; j++) b[j] = Bs[k][tx * 4 + j];
#pragma unroll
            for (int i = 0; i < 4; i++)
#pragma unroll
                for (int j = 0; j < 4; j++) acc[i][j] += a[i] * b[j];
        }
        __syncthreads();
    }

#pragma unroll
    for (int i = 0; i < 4; i++) {
        int row = bm + ty * 4 + i;
        float dis = g_dis[row];
        float dis2 = dis * dis;
#pragma unroll
        for (int j = 0; j < 4; j++) {
            int col = bn + tx * 4 + j;
            float v = acc[i][j];
            g_h1[(size_t)row * DH + col] = v;
            g_o1[(size_t)row * DH + col] = b1[col] + dis2 * v;
        }
    }
}

// ---------------------------------------------------------------------------
// Edge aggregation layer 1: o1[dst] += h1[src] * dis[src]*dis[dst]
// One thread per (edge, float4-chunk): 64 chunks of 4 floats = 256 features.
// float4 vector LOAD for the gather; 4 scalar atomicAdd for the scatter.
// ---------------------------------------------------------------------------
__global__ void __launch_bounds__(256)
k_agg1(int E) {
    int idx = blockIdx.x * 256 + threadIdx.x;
    int e = idx >> 6;
    int c = idx & 63;
    if (e >= E) return;
    int s = g_src[e];
    int d = g_dst[e];
    float nrm = g_dis[s] * g_dis[d];
    const float4 v = *reinterpret_cast<const float4*>(&g_h1[(size_t)s * DH + c * 4]);
    float* p = &g_o1[(size_t)d * DH + c * 4];
    atomicAdd(p + 0, v.x * nrm);
    atomicAdd(p + 1, v.y * nrm);
    atomicAdd(p + 2, v.z * nrm);
    atomicAdd(p + 3, v.w * nrm);
}

// ---------------------------------------------------------------------------
// GEMM2: h2 = relu(o1)[40000,256] @ W2[256,47], fused relu on load,
// fused epilogue o2 = b2 + dis^2 * h2.
// Block: (64,4) -> 4 rows per block; W2 stays L1-resident (48 KB).
// ---------------------------------------------------------------------------
__global__ void __launch_bounds__(256)
k_gemm2(const float* __restrict__ W2, const float* __restrict__ b2) {
    __shared__ float hrow[4][DH];
    int row = blockIdx.x * 4 + threadIdx.y;

    for (int k = threadIdx.x; k < DH; k += 64)
        hrow[threadIdx.y][k] = fmaxf(g_o1[(size_t)row * DH + k], 0.0f);
    __syncthreads();

    int col = threadIdx.x;
    if (col < DOUT) {
        float acc = 0.0f;
#pragma unroll 8
        for (int k = 0; k < DH; k++)
            acc += hrow[threadIdx.y][k] * W2[k * DOUT + col];
        float dis = g_dis[row];
        g_h2[(size_t)row * DOUT + col] = acc;
        g_o2[(size_t)row * DOUT + col] = b2[col] + dis * dis * acc;
    }
}

// ---------------------------------------------------------------------------
// Edge aggregation layer 2: o2[dst] += h2[src] * nrm  (47 floats per edge)
// Thread per (edge, col) with 64-wide padding (c < 47 active).
// ---------------------------------------------------------------------------
__global__ void __launch_bounds__(256)
k_agg2(int E) {
    int idx = blockIdx.x * 256 + threadIdx.x;
    int e = idx >> 6;
    int c = idx & 63;
    if (e >= E || c >= DOUT) return;
    int s = g_src[e];
    int d = g_dst[e];
    float nrm = g_dis[s] * g_dis[d];
    atomicAdd(&g_o2[(size_t)d * DOUT + c], g_h2[(size_t)s * DOUT + c] * nrm);
}

// ---------------------------------------------------------------------------
// Row-wise log_softmax over 47 classes. One warp per row.
// ---------------------------------------------------------------------------
__global__ void __launch_bounds__(256)
k_lsm(float* __restrict__ out) {
    int warp = threadIdx.x >> 5;
    int lane = threadIdx.x & 31;
    int row = blockIdx.x * 8 + warp;
    if (row >= N_NODES) return;
    const float* p = &g_o2[(size_t)row * DOUT];

    float x0 = (lane < DOUT) ? p[lane] : -INFINITY;
    float x1 = (lane + 32 < DOUT) ? p[lane + 32] : -INFINITY;
    float m = fmaxf(x0, x1);
#pragma unroll
    for (int o = 16; o; o >>= 1) m = fmaxf(m, __shfl_xor_sync(0xFFFFFFFFu, m, o));
    float s = ((lane < DOUT) ? __expf(x0 - m) : 0.0f) +
              ((lane + 32 < DOUT) ? __expf(x1 - m) : 0.0f);
#pragma unroll
    for (int o = 16; o; o >>= 1) s += __shfl_xor_sync(0xFFFFFFFFu, s, o);
    float lg = logf(s);
    if (lane < DOUT) out[(size_t)row * DOUT + lane] = x0 - m - lg;
    if (lane + 32 < DOUT) out[(size_t)row * DOUT + lane + 32] = x1 - m - lg;
}

// ---------------------------------------------------------------------------
extern "C" void kernel_launch(void* const* d_in, const int* in_sizes, int n_in,
                              void* d_out, int out_size) {
    const float* x  = (const float*)d_in[0];
    const int*   ew = (const int*)d_in[1];    // edge_index words (int32 view)
    const float* W1 = (const float*)d_in[2];
    const float* b1 = (const float*)d_in[3];
    const float* W2 = (const float*)d_in[4];
    const float* b2 = (const float*)d_in[5];
    float* out = (float*)d_out;
    const int E = in_sizes[1] / 2;   // element count is dtype-invariant

    // Decode edge_index dtype, normalize indices to int32.
    k_detect_init<<<1, 1>>>();
    k_detect<<<(E + 255) / 256, 256>>>(ew, 2 * E);
    k_extract<<<(E + 255) / 256, 256>>>(ew, E);

    k_zero_deg<<<(N_NODES + 255) / 256, 256>>>();
    k_count_deg<<<(E + 255) / 256, 256>>>(E);
    k_dis<<<(N_NODES + 255) / 256, 256>>>();

    dim3 g1(DH / 64, N_NODES / 64);
    k_gemm1<<<g1, 256>>>(x, W1, b1);

    int work = E * 64;  // 64 chunks per edge
    k_agg1<<<(work + 255) / 256, 256>>>(E);

    k_gemm2<<<N_NODES / 4, dim3(64, 4)>>>(W2, b2);

    k_agg2<<<(work + 255) / 256, 256>>>(E);

    k_lsm<<<(N_NODES + 7) / 8, 256>>>(out);
}

// round 6
// speedup vs baseline: 1.2109x; 1.2109x over previous
#include <cuda_runtime.h>
#include <cuda_bf16.h>
#include <cstdint>
#include <math.h>

#define N_NODES 40000
#define DIN 512
#define DH 256
#define DOUT 47
#define MAX_E 640000

// Scratch (no cudaMalloc allowed) — __device__ globals.
__device__ __align__(16) float g_h1[N_NODES * DH];   // X @ W1
__device__ __align__(16) float g_o1[N_NODES * DH];   // aggregated layer-1 (pre-relu)
__device__ __align__(16) float g_h2[N_NODES * DOUT]; // relu(o1) @ W2
__device__ __align__(16) float g_o2[N_NODES * DOUT]; // aggregated layer-2
__device__ float g_dis[N_NODES];                     // deg^-1/2 (deg includes self-loop)
__device__ int   g_deg[N_NODES];
__device__ int   g_src[MAX_E];
__device__ int   g_dst[MAX_E];
__device__ int   g_is64;                             // 1 if edge_index is int64

// ---------------------------------------------------------------------------
// Dtype detection (int32 vs int64 edge_index), index normalization.
// ---------------------------------------------------------------------------
__global__ void k_detect_init() { g_is64 = 1; }

__global__ void k_detect(const int* __restrict__ w, int nwords2E) {
    int i = blockIdx.x * blockDim.x + threadIdx.x;
    int odd = 2 * i + 1;
    if (odd < nwords2E && w[odd] != 0) g_is64 = 0;
}

__global__ void k_extract(const int* __restrict__ w, int E) {
    int e = blockIdx.x * blockDim.x + threadIdx.x;
    if (e >= E) return;
    if (g_is64) {
        g_src[e] = w[2 * e];
        g_dst[e] = w[2 * (E + e)];
    } else {
        g_src[e] = w[e];
        g_dst[e] = w[E + e];
    }
}

// ---------------------------------------------------------------------------
// Degree / normalization
// ---------------------------------------------------------------------------
__global__ void k_zero_deg() {
    int i = blockIdx.x * blockDim.x + threadIdx.x;
    if (i < N_NODES) g_deg[i] = 0;
}

__global__ void k_count_deg(int E) {
    int i = blockIdx.x * blockDim.x + threadIdx.x;
    if (i < E) atomicAdd(&g_deg[g_dst[i]], 1);
}

__global__ void k_dis() {
    int i = blockIdx.x * blockDim.x + threadIdx.x;
    if (i < N_NODES) g_dis[i] = rsqrtf((float)g_deg[i] + 1.0f);  // +1 = self loop
}

// ---------------------------------------------------------------------------
// TF32 helpers
// ---------------------------------------------------------------------------
__device__ __forceinline__ uint32_t f2tf32(float f) {
    uint32_t u;
    asm("cvt.rna.tf32.f32 %0, %1;" : "=r"(u) : "f"(f));
    return u;
}

__device__ __forceinline__ void mma_tf32(float* c, const uint32_t* a, const uint32_t* b) {
    asm volatile(
        "mma.sync.aligned.m16n8k8.row.col.f32.tf32.tf32.f32 "
        "{%0,%1,%2,%3}, {%4,%5,%6,%7}, {%8,%9}, {%0,%1,%2,%3};"
        : "+f"(c[0]), "+f"(c[1]), "+f"(c[2]), "+f"(c[3])
        : "r"(a[0]), "r"(a[1]), "r"(a[2]), "r"(a[3]),
          "r"(b[0]), "r"(b[1]));
}

// ---------------------------------------------------------------------------
// GEMM1 (TF32 tensor cores): h1 = X[40000,512] @ W1[512,256]
// Fused epilogue: o1 = b1 + dis[row]^2 * h1.
// Block 64x64, 4 warps (2x2), warp tile 32x32, BK=32, m16n8k8.
// SMEM padding chosen for conflict-free fragment loads:
//   As[64][36]: addr%32 = 4*gid + tig  (distinct over warp)
//   Bs[32][72]: addr%32 = 8*tig + gid  (distinct over warp)
// ---------------------------------------------------------------------------
__global__ void __launch_bounds__(128)
k_gemm1(const float* __restrict__ A,   // X
        const float* __restrict__ B,   // W1
        const float* __restrict__ b1) {
    __shared__ uint32_t As[64][36];
    __shared__ uint32_t Bs[32][72];

    const int tid = threadIdx.x;
    const int warp = tid >> 5, lane = tid & 31;
    const int gid = lane >> 2, tig = lane & 3;
    const int warpRow = warp >> 1, warpCol = warp & 1;
    const int bm = blockIdx.y * 64;
    const int bn = blockIdx.x * 64;

    float acc[2][4][4];
#pragma unroll
    for (int mi = 0; mi < 2; mi++)
#pragma unroll
        for (int ni = 0; ni < 4; ni++)
#pragma unroll
            for (int r = 0; r < 4; r++) acc[mi][ni][r] = 0.0f;

    for (int k0 = 0; k0 < DIN; k0 += 32) {
        // Load A tile: 64 rows x 32 k. 2 threads/row, 4 float4 each.
        {
            int r = tid >> 1;
            int cb = (tid & 1) * 16;
            const float4* src = reinterpret_cast<const float4*>(
                &A[(size_t)(bm + r) * DIN + k0 + cb]);
#pragma unroll
            for (int i = 0; i < 4; i++) {
                float4 v = src[i];
                int c = cb + i * 4;
                As[r][c + 0] = f2tf32(v.x);
                As[r][c + 1] = f2tf32(v.y);
                As[r][c + 2] = f2tf32(v.z);
                As[r][c + 3] = f2tf32(v.w);
            }
        }
        // Load B tile: 32 k-rows x 64 cols. 4 threads/row, 4 float4 each.
        {
            int r = tid >> 2;
            int cb = (tid & 3) * 4;
#pragma unroll
            for (int i = 0; i < 4; i++) {
                int c = cb + i * 16;
                float4 v = *reinterpret_cast<const float4*>(
                    &B[(size_t)(k0 + r) * DH + bn + c]);
                Bs[r][c + 0] = f2tf32(v.x);
                Bs[r][c + 1] = f2tf32(v.y);
                Bs[r][c + 2] = f2tf32(v.z);
                Bs[r][c + 3] = f2tf32(v.w);
            }
        }
        __syncthreads();

#pragma unroll
        for (int kk = 0; kk < 4; kk++) {
            uint32_t a[2][4], b[4][2];
            int kc = kk * 8 + tig;
#pragma unroll
            for (int mi = 0; mi < 2; mi++) {
                int r = warpRow * 32 + mi * 16 + gid;
                a[mi][0] = As[r][kc];
                a[mi][1] = As[r + 8][kc];
                a[mi][2] = As[r][kc + 4];
                a[mi][3] = As[r + 8][kc + 4];
            }
#pragma unroll
            for (int ni = 0; ni < 4; ni++) {
                int c = warpCol * 32 + ni * 8 + gid;
                b[ni][0] = Bs[kc][c];
                b[ni][1] = Bs[kc + 4][c];
            }
#pragma unroll
            for (int mi = 0; mi < 2; mi++)
#pragma unroll
                for (int ni = 0; ni < 4; ni++)
                    mma_tf32(acc[mi][ni], a[mi], b[ni]);
        }
        __syncthreads();
    }

    // Epilogue: write h1 and o1 = b1 + dis^2 * h1. c0,c1 adjacent cols.
#pragma unroll
    for (int mi = 0; mi < 2; mi++) {
        int row0 = bm + warpRow * 32 + mi * 16 + gid;
        int row1 = row0 + 8;
        float dA = g_dis[row0]; dA *= dA;
        float dB = g_dis[row1]; dB *= dB;
#pragma unroll
        for (int ni = 0; ni < 4; ni++) {
            int col = bn + warpCol * 32 + ni * 8 + tig * 2;
            float2 bb = *reinterpret_cast<const float2*>(&b1[col]);
            float v0 = acc[mi][ni][0], v1 = acc[mi][ni][1];
            float v2 = acc[mi][ni][2], v3 = acc[mi][ni][3];
            *reinterpret_cast<float2*>(&g_h1[(size_t)row0 * DH + col]) = make_float2(v0, v1);
            *reinterpret_cast<float2*>(&g_h1[(size_t)row1 * DH + col]) = make_float2(v2, v3);
            *reinterpret_cast<float2*>(&g_o1[(size_t)row0 * DH + col]) =
                make_float2(bb.x + dA * v0, bb.y + dA * v1);
            *reinterpret_cast<float2*>(&g_o1[(size_t)row1 * DH + col]) =
                make_float2(bb.x + dB * v2, bb.y + dB * v3);
        }
    }
}

// ---------------------------------------------------------------------------
// Edge aggregation layer 1: o1[dst] += h1[src] * dis[src]*dis[dst]
// One thread per (edge, float4-chunk). float4 gather + 4 scalar atomicAdd.
// ---------------------------------------------------------------------------
__global__ void __launch_bounds__(256)
k_agg1(int E) {
    int idx = blockIdx.x * 256 + threadIdx.x;
    int e = idx >> 6;
    int c = idx & 63;
    if (e >= E) return;
    int s = g_src[e];
    int d = g_dst[e];
    float nrm = g_dis[s] * g_dis[d];
    const float4 v = *reinterpret_cast<const float4*>(&g_h1[(size_t)s * DH + c * 4]);
    float* p = &g_o1[(size_t)d * DH + c * 4];
    atomicAdd(p + 0, v.x * nrm);
    atomicAdd(p + 1, v.y * nrm);
    atomicAdd(p + 2, v.z * nrm);
    atomicAdd(p + 3, v.w * nrm);
}

// ---------------------------------------------------------------------------
// GEMM2: h2 = relu(o1)[40000,256] @ W2[256,47], fused relu on load,
// fused epilogue o2 = b2 + dis^2 * h2.
// ---------------------------------------------------------------------------
__global__ void __launch_bounds__(256)
k_gemm2(const float* __restrict__ W2, const float* __restrict__ b2) {
    __shared__ float hrow[4][DH];
    int row = blockIdx.x * 4 + threadIdx.y;

    for (int k = threadIdx.x; k < DH; k += 64)
        hrow[threadIdx.y][k] = fmaxf(g_o1[(size_t)row * DH + k], 0.0f);
    __syncthreads();

    int col = threadIdx.x;
    if (col < DOUT) {
        float acc = 0.0f;
#pragma unroll 8
        for (int k = 0; k < DH; k++)
            acc += hrow[threadIdx.y][k] * W2[k * DOUT + col];
        float dis = g_dis[row];
        g_h2[(size_t)row * DOUT + col] = acc;
        g_o2[(size_t)row * DOUT + col] = b2[col] + dis * dis * acc;
    }
}

// ---------------------------------------------------------------------------
// Edge aggregation layer 2: o2[dst] += h2[src] * nrm  (47 floats per edge)
// ---------------------------------------------------------------------------
__global__ void __launch_bounds__(256)
k_agg2(int E) {
    int idx = blockIdx.x * 256 + threadIdx.x;
    int e = idx >> 6;
    int c = idx & 63;
    if (e >= E || c >= DOUT) return;
    int s = g_src[e];
    int d = g_dst[e];
    float nrm = g_dis[s] * g_dis[d];
    atomicAdd(&g_o2[(size_t)d * DOUT + c], g_h2[(size_t)s * DOUT + c] * nrm);
}

// ---------------------------------------------------------------------------
// Row-wise log_softmax over 47 classes. One warp per row.
// ---------------------------------------------------------------------------
__global__ void __launch_bounds__(256)
k_lsm(float* __restrict__ out) {
    int warp = threadIdx.x >> 5;
    int lane = threadIdx.x & 31;
    int row = blockIdx.x * 8 + warp;
    if (row >= N_NODES) return;
    const float* p = &g_o2[(size_t)row * DOUT];

    float x0 = (lane < DOUT) ? p[lane] : -INFINITY;
    float x1 = (lane + 32 < DOUT) ? p[lane + 32] : -INFINITY;
    float m = fmaxf(x0, x1);
#pragma unroll
    for (int o = 16; o; o >>= 1) m = fmaxf(m, __shfl_xor_sync(0xFFFFFFFFu, m, o));
    float s = ((lane < DOUT) ? __expf(x0 - m) : 0.0f) +
              ((lane + 32 < DOUT) ? __expf(x1 - m) : 0.0f);
#pragma unroll
    for (int o = 16; o; o >>= 1) s += __shfl_xor_sync(0xFFFFFFFFu, s, o);
    float lg = logf(s);
    if (lane < DOUT) out[(size_t)row * DOUT + lane] = x0 - m - lg;
    if (lane + 32 < DOUT) out[(size_t)row * DOUT + lane + 32] = x1 - m - lg;
}

// ---------------------------------------------------------------------------
extern "C" void kernel_launch(void* const* d_in, const int* in_sizes, int n_in,
                              void* d_out, int out_size) {
    const float* x  = (const float*)d_in[0];
    const int*   ew = (const int*)d_in[1];    // edge_index words (int32 view)
    const float* W1 = (const float*)d_in[2];
    const float* b1 = (const float*)d_in[3];
    const float* W2 = (const float*)d_in[4];
    const float* b2 = (const float*)d_in[5];
    float* out = (float*)d_out;
    const int E = in_sizes[1] / 2;

    k_detect_init<<<1, 1>>>();
    k_detect<<<(E + 255) / 256, 256>>>(ew, 2 * E);
    k_extract<<<(E + 255) / 256, 256>>>(ew, E);

    k_zero_deg<<<(N_NODES + 255) / 256, 256>>>();
    k_count_deg<<<(E + 255) / 256, 256>>>(E);
    k_dis<<<(N_NODES + 255) / 256, 256>>>();

    dim3 g1(DH / 64, N_NODES / 64);
    k_gemm1<<<g1, 128>>>(x, W1, b1);

    int work = E * 64;  // 64 chunks per edge
    k_agg1<<<(work + 255) / 256, 256>>>(E);

    k_gemm2<<<N_NODES / 4, dim3(64, 4)>>>(W2, b2);

    k_agg2<<<(work + 255) / 256, 256>>>(E);

    k_lsm<<<(N_NODES + 7) / 8, 256>>>(out);
}

// round 7
// speedup vs baseline: 1.9971x; 1.6492x over previous
#include <cuda_runtime.h>
#include <cuda_bf16.h>
#include <cstdint>
#include <math.h>

#define N_NODES 40000
#define DIN 512
#define DH 256
#define DOUT 47
#define DP 48            // padded layer-2 width (multiple of 4 for v4 atomics)
#define MAX_E 640000

// Scratch (no cudaMalloc allowed) — __device__ globals.
__device__ __align__(16) float g_h1[N_NODES * DH];   // X @ W1
__device__ __align__(16) float g_o1[N_NODES * DH];   // aggregated layer-1 (pre-relu)
__device__ __align__(16) float g_h2[N_NODES * DP];   // relu(o1) @ W2 (padded)
__device__ __align__(16) float g_o2[N_NODES * DP];   // aggregated layer-2 (padded)
__device__ float g_dis[N_NODES];                     // deg^-1/2 (deg includes self-loop)
__device__ int   g_deg[N_NODES];
__device__ int   g_src[MAX_E];
__device__ int   g_dst[MAX_E];
__device__ int   g_is64;                             // 1 if edge_index is int64

// Vectorized global reduction (sm_90+). Explicit global-space address.
__device__ __forceinline__ void red_v4(float* p, float a, float b, float c, float d) {
    unsigned long long gp = (unsigned long long)__cvta_generic_to_global(p);
    asm volatile("red.global.add.v4.f32 [%0], {%1, %2, %3, %4};"
                 :: "l"(gp), "f"(a), "f"(b), "f"(c), "f"(d) : "memory");
}

// ---------------------------------------------------------------------------
// Dtype detection (int32 vs int64 edge_index), index normalization.
// ---------------------------------------------------------------------------
__global__ void k_detect_init() { g_is64 = 1; }

__global__ void k_detect(const int* __restrict__ w, int nwords2E) {
    int i = blockIdx.x * blockDim.x + threadIdx.x;
    int odd = 2 * i + 1;
    if (odd < nwords2E && w[odd] != 0) g_is64 = 0;
}

__global__ void k_extract(const int* __restrict__ w, int E) {
    int e = blockIdx.x * blockDim.x + threadIdx.x;
    if (e >= E) return;
    if (g_is64) {
        g_src[e] = w[2 * e];
        g_dst[e] = w[2 * (E + e)];
    } else {
        g_src[e] = w[e];
        g_dst[e] = w[E + e];
    }
}

// ---------------------------------------------------------------------------
// Degree / normalization
// ---------------------------------------------------------------------------
__global__ void k_zero_deg() {
    int i = blockIdx.x * blockDim.x + threadIdx.x;
    if (i < N_NODES) g_deg[i] = 0;
}

__global__ void k_count_deg(int E) {
    int i = blockIdx.x * blockDim.x + threadIdx.x;
    if (i < E) atomicAdd(&g_deg[g_dst[i]], 1);
}

__global__ void k_dis() {
    int i = blockIdx.x * blockDim.x + threadIdx.x;
    if (i < N_NODES) g_dis[i] = rsqrtf((float)g_deg[i] + 1.0f);  // +1 = self loop
}

// ---------------------------------------------------------------------------
// TF32 helpers
// ---------------------------------------------------------------------------
__device__ __forceinline__ uint32_t f2tf32(float f) {
    uint32_t u;
    asm("cvt.rna.tf32.f32 %0, %1;" : "=r"(u) : "f"(f));
    return u;
}

__device__ __forceinline__ void mma_tf32(float* c, const uint32_t* a, const uint32_t* b) {
    asm volatile(
        "mma.sync.aligned.m16n8k8.row.col.f32.tf32.tf32.f32 "
        "{%0,%1,%2,%3}, {%4,%5,%6,%7}, {%8,%9}, {%0,%1,%2,%3};"
        : "+f"(c[0]), "+f"(c[1]), "+f"(c[2]), "+f"(c[3])
        : "r"(a[0]), "r"(a[1]), "r"(a[2]), "r"(a[3]),
          "r"(b[0]), "r"(b[1]));
}

// ---------------------------------------------------------------------------
// GEMM1 (TF32 tensor cores): h1 = X[40000,512] @ W1[512,256]
// Fused epilogue: o1 = b1 + dis[row]^2 * h1.
// Block 64x64, 4 warps (2x2), warp tile 32x32, BK=32, m16n8k8.
// ---------------------------------------------------------------------------
__global__ void __launch_bounds__(128)
k_gemm1(const float* __restrict__ A,   // X
        const float* __restrict__ B,   // W1
        const float* __restrict__ b1) {
    __shared__ uint32_t As[64][36];
    __shared__ uint32_t Bs[32][72];

    const int tid = threadIdx.x;
    const int warp = tid >> 5, lane = tid & 31;
    const int gid = lane >> 2, tig = lane & 3;
    const int warpRow = warp >> 1, warpCol = warp & 1;
    const int bm = blockIdx.y * 64;
    const int bn = blockIdx.x * 64;

    float acc[2][4][4];
#pragma unroll
    for (int mi = 0; mi < 2; mi++)
#pragma unroll
        for (int ni = 0; ni < 4; ni++)
#pragma unroll
            for (int r = 0; r < 4; r++) acc[mi][ni][r] = 0.0f;

    for (int k0 = 0; k0 < DIN; k0 += 32) {
        {
            int r = tid >> 1;
            int cb = (tid & 1) * 16;
            const float4* src = reinterpret_cast<const float4*>(
                &A[(size_t)(bm + r) * DIN + k0 + cb]);
#pragma unroll
            for (int i = 0; i < 4; i++) {
                float4 v = src[i];
                int c = cb + i * 4;
                As[r][c + 0] = f2tf32(v.x);
                As[r][c + 1] = f2tf32(v.y);
                As[r][c + 2] = f2tf32(v.z);
                As[r][c + 3] = f2tf32(v.w);
            }
        }
        {
            int r = tid >> 2;
            int cb = (tid & 3) * 4;
#pragma unroll
            for (int i = 0; i < 4; i++) {
                int c = cb + i * 16;
                float4 v = *reinterpret_cast<const float4*>(
                    &B[(size_t)(k0 + r) * DH + bn + c]);
                Bs[r][c + 0] = f2tf32(v.x);
                Bs[r][c + 1] = f2tf32(v.y);
                Bs[r][c + 2] = f2tf32(v.z);
                Bs[r][c + 3] = f2tf32(v.w);
            }
        }
        __syncthreads();

#pragma unroll
        for (int kk = 0; kk < 4; kk++) {
            uint32_t a[2][4], b[4][2];
            int kc = kk * 8 + tig;
#pragma unroll
            for (int mi = 0; mi < 2; mi++) {
                int r = warpRow * 32 + mi * 16 + gid;
                a[mi][0] = As[r][kc];
                a[mi][1] = As[r + 8][kc];
                a[mi][2] = As[r][kc + 4];
                a[mi][3] = As[r + 8][kc + 4];
            }
#pragma unroll
            for (int ni = 0; ni < 4; ni++) {
                int c = warpCol * 32 + ni * 8 + gid;
                b[ni][0] = Bs[kc][c];
                b[ni][1] = Bs[kc + 4][c];
            }
#pragma unroll
            for (int mi = 0; mi < 2; mi++)
#pragma unroll
                for (int ni = 0; ni < 4; ni++)
                    mma_tf32(acc[mi][ni], a[mi], b[ni]);
        }
        __syncthreads();
    }

#pragma unroll
    for (int mi = 0; mi < 2; mi++) {
        int row0 = bm + warpRow * 32 + mi * 16 + gid;
        int row1 = row0 + 8;
        float dA = g_dis[row0]; dA *= dA;
        float dB = g_dis[row1]; dB *= dB;
#pragma unroll
        for (int ni = 0; ni < 4; ni++) {
            int col = bn + warpCol * 32 + ni * 8 + tig * 2;
            float2 bb = *reinterpret_cast<const float2*>(&b1[col]);
            float v0 = acc[mi][ni][0], v1 = acc[mi][ni][1];
            float v2 = acc[mi][ni][2], v3 = acc[mi][ni][3];
            *reinterpret_cast<float2*>(&g_h1[(size_t)row0 * DH + col]) = make_float2(v0, v1);
            *reinterpret_cast<float2*>(&g_h1[(size_t)row1 * DH + col]) = make_float2(v2, v3);
            *reinterpret_cast<float2*>(&g_o1[(size_t)row0 * DH + col]) =
                make_float2(bb.x + dA * v0, bb.y + dA * v1);
            *reinterpret_cast<float2*>(&g_o1[(size_t)row1 * DH + col]) =
                make_float2(bb.x + dB * v2, bb.y + dB * v3);
        }
    }
}

// ---------------------------------------------------------------------------
// Edge aggregation layer 1: o1[dst] += h1[src] * dis[src]*dis[dst]
// One thread per (edge, float4-chunk). float4 gather + ONE v4 reduction.
// ---------------------------------------------------------------------------
__global__ void __launch_bounds__(256)
k_agg1(int E) {
    int idx = blockIdx.x * 256 + threadIdx.x;
    int e = idx >> 6;
    int c = idx & 63;
    if (e >= E) return;
    int s = g_src[e];
    int d = g_dst[e];
    float nrm = g_dis[s] * g_dis[d];
    const float4 v = *reinterpret_cast<const float4*>(&g_h1[(size_t)s * DH + c * 4]);
    red_v4(&g_o1[(size_t)d * DH + c * 4], v.x * nrm, v.y * nrm, v.z * nrm, v.w * nrm);
}

// ---------------------------------------------------------------------------
// GEMM2: h2 = relu(o1)[40000,256] @ W2[256,47] into padded stride-48 arrays,
// fused relu on load, fused epilogue o2 = b2 + dis^2 * h2. Pad col = 0.
// ---------------------------------------------------------------------------
__global__ void __launch_bounds__(256)
k_gemm2(const float* __restrict__ W2, const float* __restrict__ b2) {
    __shared__ float hrow[4][DH];
    int row = blockIdx.x * 4 + threadIdx.y;

    for (int k = threadIdx.x; k < DH; k += 64)
        hrow[threadIdx.y][k] = fmaxf(g_o1[(size_t)row * DH + k], 0.0f);
    __syncthreads();

    int col = threadIdx.x;
    if (col < DOUT) {
        float acc = 0.0f;
#pragma unroll 8
        for (int k = 0; k < DH; k++)
            acc += hrow[threadIdx.y][k] * W2[k * DOUT + col];
        float dis = g_dis[row];
        g_h2[(size_t)row * DP + col] = acc;
        g_o2[(size_t)row * DP + col] = b2[col] + dis * dis * acc;
    } else if (col == DOUT) {  // zero the pad column so v4 adds are no-ops
        g_h2[(size_t)row * DP + DOUT] = 0.0f;
        g_o2[(size_t)row * DP + DOUT] = 0.0f;
    }
}

// ---------------------------------------------------------------------------
// Edge aggregation layer 2 (padded width 48): 12 v4 reductions per edge.
// Thread map: idx>>4 = edge, idx&15 = chunk (chunks 12..15 idle).
// ---------------------------------------------------------------------------
__global__ void __launch_bounds__(256)
k_agg2(int E) {
    int idx = blockIdx.x * 256 + threadIdx.x;
    int e = idx >> 4;
    int c = idx & 15;
    if (e >= E || c >= (DP / 4)) return;
    int s = g_src[e];
    int d = g_dst[e];
    float nrm = g_dis[s] * g_dis[d];
    const float4 v = *reinterpret_cast<const float4*>(&g_h2[(size_t)s * DP + c * 4]);
    red_v4(&g_o2[(size_t)d * DP + c * 4], v.x * nrm, v.y * nrm, v.z * nrm, v.w * nrm);
}

// ---------------------------------------------------------------------------
// Row-wise log_softmax over 47 classes (stride-48 input). One warp per row.
// ---------------------------------------------------------------------------
__global__ void __launch_bounds__(256)
k_lsm(float* __restrict__ out) {
    int warp = threadIdx.x >> 5;
    int lane = threadIdx.x & 31;
    int row = blockIdx.x * 8 + warp;
    if (row >= N_NODES) return;
    const float* p = &g_o2[(size_t)row * DP];

    float x0 = (lane < DOUT) ? p[lane] : -INFINITY;
    float x1 = (lane + 32 < DOUT) ? p[lane + 32] : -INFINITY;
    float m = fmaxf(x0, x1);
#pragma unroll
    for (int o = 16; o; o >>= 1) m = fmaxf(m, __shfl_xor_sync(0xFFFFFFFFu, m, o));
    float s = ((lane < DOUT) ? __expf(x0 - m) : 0.0f) +
              ((lane + 32 < DOUT) ? __expf(x1 - m) : 0.0f);
#pragma unroll
    for (int o = 16; o; o >>= 1) s += __shfl_xor_sync(0xFFFFFFFFu, s, o);
    float lg = logf(s);
    if (lane < DOUT) out[(size_t)row * DOUT + lane] = x0 - m - lg;
    if (lane + 32 < DOUT) out[(size_t)row * DOUT + lane + 32] = x1 - m - lg;
}

// ---------------------------------------------------------------------------
extern "C" void kernel_launch(void* const* d_in, const int* in_sizes, int n_in,
                              void* d_out, int out_size) {
    const float* x  = (const float*)d_in[0];
    const int*   ew = (const int*)d_in[1];    // edge_index words (int32 view)
    const float* W1 = (const float*)d_in[2];
    const float* b1 = (const float*)d_in[3];
    const float* W2 = (const float*)d_in[4];
    const float* b2 = (const float*)d_in[5];
    float* out = (float*)d_out;
    const int E = in_sizes[1] / 2;

    k_detect_init<<<1, 1>>>();
    k_detect<<<(E + 255) / 256, 256>>>(ew, 2 * E);
    k_extract<<<(E + 255) / 256, 256>>>(ew, E);

    k_zero_deg<<<(N_NODES + 255) / 256, 256>>>();
    k_count_deg<<<(E + 255) / 256, 256>>>(E);
    k_dis<<<(N_NODES + 255) / 256, 256>>>();

    dim3 g1(DH / 64, N_NODES / 64);
    k_gemm1<<<g1, 128>>>(x, W1, b1);

    int work1 = E * 64;   // 64 v4-chunks per edge
    k_agg1<<<(work1 + 255) / 256, 256>>>(E);

    k_gemm2<<<N_NODES / 4, dim3(64, 4)>>>(W2, b2);

    int work2 = E * 16;   // 16 slots per edge (12 active)
    k_agg2<<<(work2 + 255) / 256, 256>>>(E);

    k_lsm<<<(N_NODES + 7) / 8, 256>>>(out);
}

// round 8
// speedup vs baseline: 2.2634x; 1.1333x over previous
#include <cuda_runtime.h>
#include <cuda_bf16.h>
#include <cstdint>
#include <math.h>

#define N_NODES 40000
#define DIN 512
#define DH 256
#define DOUT 47
#define DP 48            // padded layer-2 width (multiple of 4 for v4 atomics)
#define MAX_E 640000

// Scratch (no cudaMalloc allowed) — __device__ globals.
__device__ __align__(16) float g_h1[N_NODES * DH];   // X @ W1
__device__ __align__(16) float g_o1[N_NODES * DH];   // aggregated layer-1 (pre-relu)
__device__ __align__(16) float g_h2[N_NODES * DP];   // relu(o1) @ W2 (padded)
__device__ __align__(16) float g_o2[N_NODES * DP];   // aggregated layer-2 (padded)
__device__ float g_dis[N_NODES];                     // deg^-1/2 (deg includes self-loop)
__device__ int   g_deg[N_NODES];
__device__ int   g_src[MAX_E];
__device__ int   g_dst[MAX_E];
__device__ int   g_is64;                             // 1 if edge_index is int64

// Vectorized global reduction (sm_90+). Explicit global-space address.
__device__ __forceinline__ void red_v4(float* p, float a, float b, float c, float d) {
    unsigned long long gp = (unsigned long long)__cvta_generic_to_global(p);
    asm volatile("red.global.add.v4.f32 [%0], {%1, %2, %3, %4};"
                 :: "l"(gp), "f"(a), "f"(b), "f"(c), "f"(d) : "memory");
}

__device__ __forceinline__ void cp16(void* smem_dst, const void* gsrc) {
    uint32_t s = (uint32_t)__cvta_generic_to_shared(smem_dst);
    asm volatile("cp.async.cg.shared.global [%0], [%1], 16;" :: "r"(s), "l"(gsrc));
}

// ---------------------------------------------------------------------------
// Dtype detection (int32 vs int64 edge_index), index normalization.
// ---------------------------------------------------------------------------
__global__ void k_detect_init() { g_is64 = 1; }

__global__ void k_detect(const int* __restrict__ w, int nwords2E) {
    int i = blockIdx.x * blockDim.x + threadIdx.x;
    int odd = 2 * i + 1;
    if (odd < nwords2E && w[odd] != 0) g_is64 = 0;
}

__global__ void k_extract(const int* __restrict__ w, int E) {
    int e = blockIdx.x * blockDim.x + threadIdx.x;
    if (e >= E) return;
    if (g_is64) {
        g_src[e] = w[2 * e];
        g_dst[e] = w[2 * (E + e)];
    } else {
        g_src[e] = w[e];
        g_dst[e] = w[E + e];
    }
}

// ---------------------------------------------------------------------------
// Degree / normalization
// ---------------------------------------------------------------------------
__global__ void k_zero_deg() {
    int i = blockIdx.x * blockDim.x + threadIdx.x;
    if (i < N_NODES) g_deg[i] = 0;
}

__global__ void k_count_deg(int E) {
    int i = blockIdx.x * blockDim.x + threadIdx.x;
    if (i < E) atomicAdd(&g_deg[g_dst[i]], 1);
}

__global__ void k_dis() {
    int i = blockIdx.x * blockDim.x + threadIdx.x;
    if (i < N_NODES) g_dis[i] = rsqrtf((float)g_deg[i] + 1.0f);  // +1 = self loop
}

// ---------------------------------------------------------------------------
// TF32 helpers
// ---------------------------------------------------------------------------
__device__ __forceinline__ uint32_t f2tf32(float f) {
    uint32_t u;
    asm("cvt.rna.tf32.f32 %0, %1;" : "=r"(u) : "f"(f));
    return u;
}

__device__ __forceinline__ void mma_tf32(float* c, const uint32_t* a, const uint32_t* b) {
    asm volatile(
        "mma.sync.aligned.m16n8k8.row.col.f32.tf32.tf32.f32 "
        "{%0,%1,%2,%3}, {%4,%5,%6,%7}, {%8,%9}, {%0,%1,%2,%3};"
        : "+f"(c[0]), "+f"(c[1]), "+f"(c[2]), "+f"(c[3])
        : "r"(a[0]), "r"(a[1]), "r"(a[2]), "r"(a[3]),
          "r"(b[0]), "r"(b[1]));
}

// ---------------------------------------------------------------------------
// GEMM1 (TF32, cp.async double-buffered): h1 = X[40000,512] @ W1[512,256]
// Fused epilogue: o1 = b1 + dis[row]^2 * h1.
// Block 128x128, 256 threads, 8 warps (4x2), warp tile 32x64, BK=16.
// SMEM (fp32 bits, cvt.rna on fragment load):
//   As[2][128][20]: (20*gid + tig)%32 distinct over warp -> conflict-free
//   Bs[2][16][136]: (8*tig + gid)%32 distinct over warp  -> conflict-free
// ---------------------------------------------------------------------------
#define BK1 16
#define NKT (DIN / BK1)   // 32
__global__ void __launch_bounds__(256, 2)
k_gemm1(const float* __restrict__ A,   // X
        const float* __restrict__ B,   // W1
        const float* __restrict__ b1) {
    __shared__ float As[2][128][20];
    __shared__ float Bs[2][BK1][136];

    const int tid = threadIdx.x;
    const int warp = tid >> 5, lane = tid & 31;
    const int gid = lane >> 2, tig = lane & 3;
    const int warpRow = warp >> 1, warpCol = warp & 1;
    const int bm = blockIdx.y * 128;
    const int bn = blockIdx.x * 128;

    // A-load mapping: 128 rows x 16 k = 512 16B-chunks; thread does 2.
    const int a_r0 = tid >> 2,           a_c0 = (tid & 3) * 4;
    const int a_r1 = (tid + 256) >> 2,   a_c1 = a_c0;
    const int a_g0 = (bm + a_r0 < N_NODES) ? bm + a_r0 : N_NODES - 1;
    const int a_g1 = (bm + a_r1 < N_NODES) ? bm + a_r1 : N_NODES - 1;
    // B-load mapping: 16 rows x 128 = 512 chunks; thread does 2.
    const int b_r0 = tid >> 5,           b_c0 = (tid & 31) * 4;
    const int b_r1 = (tid + 256) >> 5,   b_c1 = b_c0;

    float acc[2][8][4];
#pragma unroll
    for (int mi = 0; mi < 2; mi++)
#pragma unroll
        for (int ni = 0; ni < 8; ni++)
#pragma unroll
            for (int r = 0; r < 4; r++) acc[mi][ni][r] = 0.0f;

    // Prologue: tile 0 into buf 0.
    {
        cp16(&As[0][a_r0][a_c0], &A[(size_t)a_g0 * DIN + a_c0]);
        cp16(&As[0][a_r1][a_c1], &A[(size_t)a_g1 * DIN + a_c1]);
        cp16(&Bs[0][b_r0][b_c0], &B[(size_t)b_r0 * DH + bn + b_c0]);
        cp16(&Bs[0][b_r1][b_c1], &B[(size_t)b_r1 * DH + bn + b_c1]);
        asm volatile("cp.async.commit_group;");
    }

    int buf = 0;
    for (int kt = 0; kt < NKT; kt++) {
        if (kt + 1 < NKT) {
            int k0 = (kt + 1) * BK1;
            int nb = buf ^ 1;
            cp16(&As[nb][a_r0][a_c0], &A[(size_t)a_g0 * DIN + k0 + a_c0]);
            cp16(&As[nb][a_r1][a_c1], &A[(size_t)a_g1 * DIN + k0 + a_c1]);
            cp16(&Bs[nb][b_r0][b_c0], &B[(size_t)(k0 + b_r0) * DH + bn + b_c0]);
            cp16(&Bs[nb][b_r1][b_c1], &B[(size_t)(k0 + b_r1) * DH + bn + b_c1]);
            asm volatile("cp.async.commit_group;");
            asm volatile("cp.async.wait_group 1;");
        } else {
            asm volatile("cp.async.wait_group 0;");
        }
        __syncthreads();

#pragma unroll
        for (int kk = 0; kk < 2; kk++) {
            int kc = kk * 8 + tig;
            uint32_t a[2][4], b[8][2];
#pragma unroll
            for (int mi = 0; mi < 2; mi++) {
                int r = warpRow * 32 + mi * 16 + gid;
                a[mi][0] = f2tf32(As[buf][r][kc]);
                a[mi][1] = f2tf32(As[buf][r + 8][kc]);
                a[mi][2] = f2tf32(As[buf][r][kc + 4]);
                a[mi][3] = f2tf32(As[buf][r + 8][kc + 4]);
            }
#pragma unroll
            for (int ni = 0; ni < 8; ni++) {
                int c = warpCol * 64 + ni * 8 + gid;
                b[ni][0] = f2tf32(Bs[buf][kc][c]);
                b[ni][1] = f2tf32(Bs[buf][kc + 4][c]);
            }
#pragma unroll
            for (int mi = 0; mi < 2; mi++)
#pragma unroll
                for (int ni = 0; ni < 8; ni++)
                    mma_tf32(acc[mi][ni], a[mi], b[ni]);
        }
        __syncthreads();
        buf ^= 1;
    }

    // Epilogue: write h1 and o1 = b1 + dis^2 * h1 (guard M edge).
#pragma unroll
    for (int mi = 0; mi < 2; mi++) {
        int row0 = bm + warpRow * 32 + mi * 16 + gid;
        int row1 = row0 + 8;
        bool v0ok = row0 < N_NODES, v1ok = row1 < N_NODES;
        float dA = v0ok ? g_dis[row0] : 0.0f; dA *= dA;
        float dB = v1ok ? g_dis[row1] : 0.0f; dB *= dB;
#pragma unroll
        for (int ni = 0; ni < 8; ni++) {
            int col = bn + warpCol * 64 + ni * 8 + tig * 2;
            float2 bb = *reinterpret_cast<const float2*>(&b1[col]);
            float v0 = acc[mi][ni][0], v1 = acc[mi][ni][1];
            float v2 = acc[mi][ni][2], v3 = acc[mi][ni][3];
            if (v0ok) {
                *reinterpret_cast<float2*>(&g_h1[(size_t)row0 * DH + col]) = make_float2(v0, v1);
                *reinterpret_cast<float2*>(&g_o1[(size_t)row0 * DH + col]) =
                    make_float2(bb.x + dA * v0, bb.y + dA * v1);
            }
            if (v1ok) {
                *reinterpret_cast<float2*>(&g_h1[(size_t)row1 * DH + col]) = make_float2(v2, v3);
                *reinterpret_cast<float2*>(&g_o1[(size_t)row1 * DH + col]) =
                    make_float2(bb.x + dB * v2, bb.y + dB * v3);
            }
        }
    }
}

// ---------------------------------------------------------------------------
// Edge aggregation layer 1: o1[dst] += h1[src] * dis[src]*dis[dst]
// One thread per (edge, float4-chunk). float4 gather + ONE v4 reduction.
// ---------------------------------------------------------------------------
__global__ void __launch_bounds__(256)
k_agg1(int E) {
    int idx = blockIdx.x * 256 + threadIdx.x;
    int e = idx >> 6;
    int c = idx & 63;
    if (e >= E) return;
    int s = g_src[e];
    int d = g_dst[e];
    float nrm = g_dis[s] * g_dis[d];
    const float4 v = *reinterpret_cast<const float4*>(&g_h1[(size_t)s * DH + c * 4]);
    red_v4(&g_o1[(size_t)d * DH + c * 4], v.x * nrm, v.y * nrm, v.z * nrm, v.w * nrm);
}

// ---------------------------------------------------------------------------
// GEMM2: h2 = relu(o1)[40000,256] @ W2[256,47] into padded stride-48 arrays,
// fused relu on load, fused epilogue o2 = b2 + dis^2 * h2. Pad col = 0.
// ---------------------------------------------------------------------------
__global__ void __launch_bounds__(256)
k_gemm2(const float* __restrict__ W2, const float* __restrict__ b2) {
    __shared__ float hrow[4][DH];
    int row = blockIdx.x * 4 + threadIdx.y;

    for (int k = threadIdx.x; k < DH; k += 64)
        hrow[threadIdx.y][k] = fmaxf(g_o1[(size_t)row * DH + k], 0.0f);
    __syncthreads();

    int col = threadIdx.x;
    if (col < DOUT) {
        float acc = 0.0f;
#pragma unroll 8
        for (int k = 0; k < DH; k++)
            acc += hrow[threadIdx.y][k] * W2[k * DOUT + col];
        float dis = g_dis[row];
        g_h2[(size_t)row * DP + col] = acc;
        g_o2[(size_t)row * DP + col] = b2[col] + dis * dis * acc;
    } else if (col == DOUT) {  // zero the pad column so v4 adds are no-ops
        g_h2[(size_t)row * DP + DOUT] = 0.0f;
        g_o2[(size_t)row * DP + DOUT] = 0.0f;
    }
}

// ---------------------------------------------------------------------------
// Edge aggregation layer 2 (padded width 48): 12 v4 reductions per edge.
// ---------------------------------------------------------------------------
__global__ void __launch_bounds__(256)
k_agg2(int E) {
    int idx = blockIdx.x * 256 + threadIdx.x;
    int e = idx >> 4;
    int c = idx & 15;
    if (e >= E || c >= (DP / 4)) return;
    int s = g_src[e];
    int d = g_dst[e];
    float nrm = g_dis[s] * g_dis[d];
    const float4 v = *reinterpret_cast<const float4*>(&g_h2[(size_t)s * DP + c * 4]);
    red_v4(&g_o2[(size_t)d * DP + c * 4], v.x * nrm, v.y * nrm, v.z * nrm, v.w * nrm);
}

// ---------------------------------------------------------------------------
// Row-wise log_softmax over 47 classes (stride-48 input). One warp per row.
// ---------------------------------------------------------------------------
__global__ void __launch_bounds__(256)
k_lsm(float* __restrict__ out) {
    int warp = threadIdx.x >> 5;
    int lane = threadIdx.x & 31;
    int row = blockIdx.x * 8 + warp;
    if (row >= N_NODES) return;
    const float* p = &g_o2[(size_t)row * DP];

    float x0 = (lane < DOUT) ? p[lane] : -INFINITY;
    float x1 = (lane + 32 < DOUT) ? p[lane + 32] : -INFINITY;
    float m = fmaxf(x0, x1);
#pragma unroll
    for (int o = 16; o; o >>= 1) m = fmaxf(m, __shfl_xor_sync(0xFFFFFFFFu, m, o));
    float s = ((lane < DOUT) ? __expf(x0 - m) : 0.0f) +
              ((lane + 32 < DOUT) ? __expf(x1 - m) : 0.0f);
#pragma unroll
    for (int o = 16; o; o >>= 1) s += __shfl_xor_sync(0xFFFFFFFFu, s, o);
    float lg = logf(s);
    if (lane < DOUT) out[(size_t)row * DOUT + lane] = x0 - m - lg;
    if (lane + 32 < DOUT) out[(size_t)row * DOUT + lane + 32] = x1 - m - lg;
}

// ---------------------------------------------------------------------------
extern "C" void kernel_launch(void* const* d_in, const int* in_sizes, int n_in,
                              void* d_out, int out_size) {
    const float* x  = (const float*)d_in[0];
    const int*   ew = (const int*)d_in[1];    // edge_index words (int32 view)
    const float* W1 = (const float*)d_in[2];
    const float* b1 = (const float*)d_in[3];
    const float* W2 = (const float*)d_in[4];
    const float* b2 = (const float*)d_in[5];
    float* out = (float*)d_out;
    const int E = in_sizes[1] / 2;

    k_detect_init<<<1, 1>>>();
    k_detect<<<(E + 255) / 256, 256>>>(ew, 2 * E);
    k_extract<<<(E + 255) / 256, 256>>>(ew, E);

    k_zero_deg<<<(N_NODES + 255) / 256, 256>>>();
    k_count_deg<<<(E + 255) / 256, 256>>>(E);
    k_dis<<<(N_NODES + 255) / 256, 256>>>();

    dim3 g1(DH / 128, (N_NODES + 127) / 128);   // 2 x 313
    k_gemm1<<<g1, 256>>>(x, W1, b1);

    int work1 = E * 64;   // 64 v4-chunks per edge
    k_agg1<<<(work1 + 255) / 256, 256>>>(E);

    k_gemm2<<<N_NODES / 4, dim3(64, 4)>>>(W2, b2);

    int work2 = E * 16;   // 16 slots per edge (12 active)
    k_agg2<<<(work2 + 255) / 256, 256>>>(E);

    k_lsm<<<(N_NODES + 7) / 8, 256>>>(out);
}

// round 9
// speedup vs baseline: 2.5425x; 1.1233x over previous
#include <cuda_runtime.h>
#include <cuda_bf16.h>
#include <cstdint>
#include <math.h>

#define N_NODES 40000
#define DIN 512
#define DH 256
#define DOUT 47
#define DP 48            // padded layer-2 width (multiple of 4)
#define MAX_E 640000

// Scratch (no cudaMalloc allowed) — __device__ globals.
__device__ __align__(16) float g_h1[N_NODES * DH];   // X @ W1
__device__ __align__(16) float g_o1[N_NODES * DH];   // aggregated layer-1 (pre-relu)
__device__ __align__(16) float g_h2[N_NODES * DP];   // relu(o1) @ W2 (padded)
__device__ float g_dis[N_NODES];                     // deg^-1/2 (deg includes self-loop)
__device__ int   g_deg[N_NODES];
__device__ int   g_src[MAX_E];
__device__ int   g_dst[MAX_E];
__device__ int   g_off[N_NODES + 1];                 // CSR row offsets (by dst)
__device__ int   g_cursor[N_NODES];                  // fill cursors
__device__ int   g_csr_src[MAX_E];                   // src indices sorted by dst
__device__ int   g_is64;                             // 1 if edge_index is int64

__device__ __forceinline__ void cp16(void* smem_dst, const void* gsrc) {
    uint32_t s = (uint32_t)__cvta_generic_to_shared(smem_dst);
    asm volatile("cp.async.cg.shared.global [%0], [%1], 16;" :: "r"(s), "l"(gsrc));
}

// ---------------------------------------------------------------------------
// Dtype detection (int32 vs int64 edge_index), index normalization.
// ---------------------------------------------------------------------------
__global__ void k_detect_init() { g_is64 = 1; }

__global__ void k_detect(const int* __restrict__ w, int nwords2E) {
    int i = blockIdx.x * blockDim.x + threadIdx.x;
    int odd = 2 * i + 1;
    if (odd < nwords2E && w[odd] != 0) g_is64 = 0;
}

__global__ void k_extract(const int* __restrict__ w, int E) {
    int e = blockIdx.x * blockDim.x + threadIdx.x;
    if (e >= E) return;
    if (g_is64) {
        g_src[e] = w[2 * e];
        g_dst[e] = w[2 * (E + e)];
    } else {
        g_src[e] = w[e];
        g_dst[e] = w[E + e];
    }
}

// ---------------------------------------------------------------------------
// Degree / normalization / CSR build
// ---------------------------------------------------------------------------
__global__ void k_zero_deg() {
    int i = blockIdx.x * blockDim.x + threadIdx.x;
    if (i < N_NODES) g_deg[i] = 0;
}

__global__ void k_count_deg(int E) {
    int i = blockIdx.x * blockDim.x + threadIdx.x;
    if (i < E) atomicAdd(&g_deg[g_dst[i]], 1);
}

__global__ void k_dis() {
    int i = blockIdx.x * blockDim.x + threadIdx.x;
    if (i < N_NODES) g_dis[i] = rsqrtf((float)g_deg[i] + 1.0f);  // +1 = self loop
}

// Single-block exclusive prefix scan over g_deg -> g_off, init cursors.
#define SCAN_T 1024
#define SCAN_PER ((N_NODES + SCAN_T - 1) / SCAN_T)   // 40
__global__ void __launch_bounds__(SCAN_T)
k_scan() {
    __shared__ int part[SCAN_T];
    int t = threadIdx.x;
    int base = t * SCAN_PER;
    int sum = 0;
#pragma unroll 4
    for (int i = 0; i < SCAN_PER; i++) {
        int idx = base + i;
        if (idx < N_NODES) sum += g_deg[idx];
    }
    part[t] = sum;
    __syncthreads();
    // Hillis-Steele inclusive scan
    for (int o = 1; o < SCAN_T; o <<= 1) {
        int v = (t >= o) ? part[t - o] : 0;
        __syncthreads();
        part[t] += v;
        __syncthreads();
    }
    int off = (t == 0) ? 0 : part[t - 1];
    for (int i = 0; i < SCAN_PER; i++) {
        int idx = base + i;
        if (idx < N_NODES) {
            g_off[idx] = off;
            g_cursor[idx] = off;
            off += g_deg[idx];
        }
    }
    if (t == SCAN_T - 1) g_off[N_NODES] = off;
}

__global__ void k_fill(int E) {
    int e = blockIdx.x * blockDim.x + threadIdx.x;
    if (e >= E) return;
    int d = g_dst[e];
    int pos = atomicAdd(&g_cursor[d], 1);
    g_csr_src[pos] = g_src[e];
}

// ---------------------------------------------------------------------------
// TF32 helpers
// ---------------------------------------------------------------------------
__device__ __forceinline__ uint32_t f2tf32(float f) {
    uint32_t u;
    asm("cvt.rna.tf32.f32 %0, %1;" : "=r"(u) : "f"(f));
    return u;
}

__device__ __forceinline__ void mma_tf32(float* c, const uint32_t* a, const uint32_t* b) {
    asm volatile(
        "mma.sync.aligned.m16n8k8.row.col.f32.tf32.tf32.f32 "
        "{%0,%1,%2,%3}, {%4,%5,%6,%7}, {%8,%9}, {%0,%1,%2,%3};"
        : "+f"(c[0]), "+f"(c[1]), "+f"(c[2]), "+f"(c[3])
        : "r"(a[0]), "r"(a[1]), "r"(a[2]), "r"(a[3]),
          "r"(b[0]), "r"(b[1]));
}

// ---------------------------------------------------------------------------
// GEMM1 (TF32, cp.async double-buffered): h1 = X[40000,512] @ W1[512,256]
// Writes h1 only (aggregation is now gather-side).
// Block 128x128, 256 threads, 8 warps (4x2), warp tile 32x64, BK=16.
// ---------------------------------------------------------------------------
#define BK1 16
#define NKT (DIN / BK1)   // 32
__global__ void __launch_bounds__(256, 2)
k_gemm1(const float* __restrict__ A,   // X
        const float* __restrict__ B) { // W1
    __shared__ float As[2][128][20];
    __shared__ float Bs[2][BK1][136];

    const int tid = threadIdx.x;
    const int warp = tid >> 5, lane = tid & 31;
    const int gid = lane >> 2, tig = lane & 3;
    const int warpRow = warp >> 1, warpCol = warp & 1;
    const int bm = blockIdx.y * 128;
    const int bn = blockIdx.x * 128;

    const int a_r0 = tid >> 2,           a_c0 = (tid & 3) * 4;
    const int a_r1 = (tid + 256) >> 2,   a_c1 = a_c0;
    const int a_g0 = (bm + a_r0 < N_NODES) ? bm + a_r0 : N_NODES - 1;
    const int a_g1 = (bm + a_r1 < N_NODES) ? bm + a_r1 : N_NODES - 1;
    const int b_r0 = tid >> 5,           b_c0 = (tid & 31) * 4;
    const int b_r1 = (tid + 256) >> 5,   b_c1 = b_c0;

    float acc[2][8][4];
#pragma unroll
    for (int mi = 0; mi < 2; mi++)
#pragma unroll
        for (int ni = 0; ni < 8; ni++)
#pragma unroll
            for (int r = 0; r < 4; r++) acc[mi][ni][r] = 0.0f;

    {
        cp16(&As[0][a_r0][a_c0], &A[(size_t)a_g0 * DIN + a_c0]);
        cp16(&As[0][a_r1][a_c1], &A[(size_t)a_g1 * DIN + a_c1]);
        cp16(&Bs[0][b_r0][b_c0], &B[(size_t)b_r0 * DH + bn + b_c0]);
        cp16(&Bs[0][b_r1][b_c1], &B[(size_t)b_r1 * DH + bn + b_c1]);
        asm volatile("cp.async.commit_group;");
    }

    int buf = 0;
    for (int kt = 0; kt < NKT; kt++) {
        if (kt + 1 < NKT) {
            int k0 = (kt + 1) * BK1;
            int nb = buf ^ 1;
            cp16(&As[nb][a_r0][a_c0], &A[(size_t)a_g0 * DIN + k0 + a_c0]);
            cp16(&As[nb][a_r1][a_c1], &A[(size_t)a_g1 * DIN + k0 + a_c1]);
            cp16(&Bs[nb][b_r0][b_c0], &B[(size_t)(k0 + b_r0) * DH + bn + b_c0]);
            cp16(&Bs[nb][b_r1][b_c1], &B[(size_t)(k0 + b_r1) * DH + bn + b_c1]);
            asm volatile("cp.async.commit_group;");
            asm volatile("cp.async.wait_group 1;");
        } else {
            asm volatile("cp.async.wait_group 0;");
        }
        __syncthreads();

#pragma unroll
        for (int kk = 0; kk < 2; kk++) {
            int kc = kk * 8 + tig;
            uint32_t a[2][4], b[8][2];
#pragma unroll
            for (int mi = 0; mi < 2; mi++) {
                int r = warpRow * 32 + mi * 16 + gid;
                a[mi][0] = f2tf32(As[buf][r][kc]);
                a[mi][1] = f2tf32(As[buf][r + 8][kc]);
                a[mi][2] = f2tf32(As[buf][r][kc + 4]);
                a[mi][3] = f2tf32(As[buf][r + 8][kc + 4]);
            }
#pragma unroll
            for (int ni = 0; ni < 8; ni++) {
                int c = warpCol * 64 + ni * 8 + gid;
                b[ni][0] = f2tf32(Bs[buf][kc][c]);
                b[ni][1] = f2tf32(Bs[buf][kc + 4][c]);
            }
#pragma unroll
            for (int mi = 0; mi < 2; mi++)
#pragma unroll
                for (int ni = 0; ni < 8; ni++)
                    mma_tf32(acc[mi][ni], a[mi], b[ni]);
        }
        __syncthreads();
        buf ^= 1;
    }

#pragma unroll
    for (int mi = 0; mi < 2; mi++) {
        int row0 = bm + warpRow * 32 + mi * 16 + gid;
        int row1 = row0 + 8;
#pragma unroll
        for (int ni = 0; ni < 8; ni++) {
            int col = bn + warpCol * 64 + ni * 8 + tig * 2;
            if (row0 < N_NODES)
                *reinterpret_cast<float2*>(&g_h1[(size_t)row0 * DH + col]) =
                    make_float2(acc[mi][ni][0], acc[mi][ni][1]);
            if (row1 < N_NODES)
                *reinterpret_cast<float2*>(&g_h1[(size_t)row1 * DH + col]) =
                    make_float2(acc[mi][ni][2], acc[mi][ni][3]);
        }
    }
}

// ---------------------------------------------------------------------------
// Layer-1 gather aggregation: o1[d] = b1 + dis[d]^2*h1[d] + sum_s nrm*h1[s]
// Block (64,4): 4 nodes per block, 64 lanes = float4 chunks of 256 features.
// ---------------------------------------------------------------------------
__global__ void __launch_bounds__(256)
k_agg1g(const float* __restrict__ b1) {
    int d = blockIdx.x * 4 + threadIdx.y;
    int c = threadIdx.x;
    float dd = g_dis[d];
    float w = dd * dd;

    float4 bb = reinterpret_cast<const float4*>(b1)[c];
    float4 h = *reinterpret_cast<const float4*>(&g_h1[(size_t)d * DH + c * 4]);
    float4 acc = make_float4(bb.x + w * h.x, bb.y + w * h.y,
                             bb.z + w * h.z, bb.w + w * h.w);

    int i = g_off[d], end = g_off[d + 1];
    for (; i < end; i++) {
        int s = g_csr_src[i];
        float nrm = g_dis[s] * dd;
        float4 v = *reinterpret_cast<const float4*>(&g_h1[(size_t)s * DH + c * 4]);
        acc.x += nrm * v.x; acc.y += nrm * v.y;
        acc.z += nrm * v.z; acc.w += nrm * v.w;
    }
    *reinterpret_cast<float4*>(&g_o1[(size_t)d * DH + c * 4]) = acc;
}

// ---------------------------------------------------------------------------
// GEMM2: h2 = relu(o1)[40000,256] @ W2[256,47] into padded stride-48 array,
// fused relu on load. Pad col = 0.
// ---------------------------------------------------------------------------
__global__ void __launch_bounds__(256)
k_gemm2(const float* __restrict__ W2) {
    __shared__ float hrow[4][DH];
    int row = blockIdx.x * 4 + threadIdx.y;

    for (int k = threadIdx.x; k < DH; k += 64)
        hrow[threadIdx.y][k] = fmaxf(g_o1[(size_t)row * DH + k], 0.0f);
    __syncthreads();

    int col = threadIdx.x;
    if (col < DOUT) {
        float acc = 0.0f;
#pragma unroll 8
        for (int k = 0; k < DH; k++)
            acc += hrow[threadIdx.y][k] * W2[k * DOUT + col];
        g_h2[(size_t)row * DP + col] = acc;
    } else if (col == DOUT) {
        g_h2[(size_t)row * DP + DOUT] = 0.0f;
    }
}

// ---------------------------------------------------------------------------
// Layer-2 gather aggregation FUSED with log-softmax.
// Block (16,16): 16 nodes per block; 16 lanes per node (12 active float4
// chunks of the padded 48-wide row). Row reductions via width-16 shuffles.
// ---------------------------------------------------------------------------
__global__ void __launch_bounds__(256)
k_agg2g(const float* __restrict__ b2, float* __restrict__ out) {
    int d = blockIdx.x * 16 + threadIdx.y;
    int c = threadIdx.x;          // 0..15; chunks 12..15 inactive
    float dd = g_dis[d];

    float4 acc = make_float4(-INFINITY, -INFINITY, -INFINITY, -INFINITY);
    int col = c * 4;
    if (c < 12) {
        float w = dd * dd;
        float4 bb;
        bb.x = b2[col];
        bb.y = b2[col + 1];
        bb.z = b2[col + 2];
        bb.w = (col + 3 < DOUT) ? b2[col + 3] : 0.0f;
        float4 h = *reinterpret_cast<const float4*>(&g_h2[(size_t)d * DP + col]);
        acc = make_float4(bb.x + w * h.x, bb.y + w * h.y,
                          bb.z + w * h.z, bb.w + w * h.w);
        int i = g_off[d], end = g_off[d + 1];
        for (; i < end; i++) {
            int s = g_csr_src[i];
            float nrm = g_dis[s] * dd;
            float4 v = *reinterpret_cast<const float4*>(&g_h2[(size_t)s * DP + col]);
            acc.x += nrm * v.x; acc.y += nrm * v.y;
            acc.z += nrm * v.z; acc.w += nrm * v.w;
        }
        if (col + 3 >= DOUT) acc.w = -INFINITY;   // pad column
    }

    // log-softmax across the 16-lane group (47 valid values).
    float m = fmaxf(fmaxf(acc.x, acc.y), fmaxf(acc.z, acc.w));
#pragma unroll
    for (int o = 8; o; o >>= 1) m = fmaxf(m, __shfl_xor_sync(0xFFFFFFFFu, m, o, 16));
    float s = __expf(acc.x - m) + __expf(acc.y - m) +
              __expf(acc.z - m) + __expf(acc.w - m);   // exp(-inf)=0
#pragma unroll
    for (int o = 8; o; o >>= 1) s += __shfl_xor_sync(0xFFFFFFFFu, s, o, 16);
    float lg = m + logf(s);

    if (c < 12) {
        float* po = &out[(size_t)d * DOUT + col];
        po[0] = acc.x - lg;
        po[1] = acc.y - lg;
        po[2] = acc.z - lg;
        if (col + 3 < DOUT) po[3] = acc.w - lg;
    }
}

// ---------------------------------------------------------------------------
extern "C" void kernel_launch(void* const* d_in, const int* in_sizes, int n_in,
                              void* d_out, int out_size) {
    const float* x  = (const float*)d_in[0];
    const int*   ew = (const int*)d_in[1];    // edge_index words (int32 view)
    const float* W1 = (const float*)d_in[2];
    const float* b1 = (const float*)d_in[3];
    const float* W2 = (const float*)d_in[4];
    const float* b2 = (const float*)d_in[5];
    float* out = (float*)d_out;
    const int E = in_sizes[1] / 2;

    k_detect_init<<<1, 1>>>();
    k_detect<<<(E + 255) / 256, 256>>>(ew, 2 * E);
    k_extract<<<(E + 255) / 256, 256>>>(ew, E);

    k_zero_deg<<<(N_NODES + 255) / 256, 256>>>();
    k_count_deg<<<(E + 255) / 256, 256>>>(E);
    k_dis<<<(N_NODES + 255) / 256, 256>>>();
    k_scan<<<1, SCAN_T>>>();
    k_fill<<<(E + 255) / 256, 256>>>(E);

    dim3 g1(DH / 128, (N_NODES + 127) / 128);
    k_gemm1<<<g1, 256>>>(x, W1);

    k_agg1g<<<N_NODES / 4, dim3(64, 4)>>>(b1);

    k_gemm2<<<N_NODES / 4, dim3(64, 4)>>>(W2);

    k_agg2g<<<N_NODES / 16, dim3(16, 16)>>>(b2, out);
}

// round 10
// speedup vs baseline: 2.6653x; 1.0483x over previous
#include <cuda_runtime.h>
#include <cuda_fp16.h>
#include <cstdint>
#include <math.h>

#define N_NODES 40000
#define DIN 512
#define DH 256
#define DOUT 47
#define DP 48            // padded layer-2 width (multiple of 4)
#define MAX_E 640000

// Scratch (no cudaMalloc allowed) — __device__ globals.
__device__ __align__(16) __half g_h1h[N_NODES * DH]; // X @ W1 (fp16 storage)
__device__ __align__(16) float  g_o1[N_NODES * DH];  // aggregated layer-1 (pre-relu)
__device__ __align__(16) __half g_h2h[N_NODES * DP]; // relu(o1) @ W2 (fp16, padded)
__device__ float g_dis[N_NODES];                     // deg^-1/2 (deg includes self-loop)
__device__ int   g_deg[N_NODES];
__device__ int   g_src[MAX_E];
__device__ int   g_dst[MAX_E];
__device__ int   g_off[N_NODES + 1];                 // CSR row offsets (by dst)
__device__ int   g_cursor[N_NODES];                  // fill cursors
__device__ int   g_csr_src[MAX_E];                   // src indices sorted by dst
__device__ int   g_is64;                             // 1 if edge_index is int64

__device__ __forceinline__ void cp16(void* smem_dst, const void* gsrc) {
    uint32_t s = (uint32_t)__cvta_generic_to_shared(smem_dst);
    asm volatile("cp.async.cg.shared.global [%0], [%1], 16;" :: "r"(s), "l"(gsrc));
}

// Load 4 consecutive halfs as 2 float2.
__device__ __forceinline__ void ldh4(const __half* p, float2& lo, float2& hi) {
    uint2 u = *reinterpret_cast<const uint2*>(p);
    lo = __half22float2(*reinterpret_cast<const __half2*>(&u.x));
    hi = __half22float2(*reinterpret_cast<const __half2*>(&u.y));
}

// ---------------------------------------------------------------------------
// Dtype detection (int32 vs int64 edge_index), index normalization.
// ---------------------------------------------------------------------------
__global__ void k_detect_init() { g_is64 = 1; }

__global__ void k_detect(const int* __restrict__ w, int nwords2E) {
    int i = blockIdx.x * blockDim.x + threadIdx.x;
    int odd = 2 * i + 1;
    if (odd < nwords2E && w[odd] != 0) g_is64 = 0;
}

__global__ void k_extract(const int* __restrict__ w, int E) {
    int e = blockIdx.x * blockDim.x + threadIdx.x;
    if (e >= E) return;
    if (g_is64) {
        g_src[e] = w[2 * e];
        g_dst[e] = w[2 * (E + e)];
    } else {
        g_src[e] = w[e];
        g_dst[e] = w[E + e];
    }
}

// ---------------------------------------------------------------------------
// Degree / normalization / CSR build
// ---------------------------------------------------------------------------
__global__ void k_zero_deg() {
    int i = blockIdx.x * blockDim.x + threadIdx.x;
    if (i < N_NODES) g_deg[i] = 0;
}

__global__ void k_count_deg(int E) {
    int i = blockIdx.x * blockDim.x + threadIdx.x;
    if (i < E) atomicAdd(&g_deg[g_dst[i]], 1);
}

__global__ void k_dis() {
    int i = blockIdx.x * blockDim.x + threadIdx.x;
    if (i < N_NODES) g_dis[i] = rsqrtf((float)g_deg[i] + 1.0f);  // +1 = self loop
}

// Single-block exclusive prefix scan over g_deg -> g_off, init cursors.
#define SCAN_T 1024
#define SCAN_PER ((N_NODES + SCAN_T - 1) / SCAN_T)   // 40
__global__ void __launch_bounds__(SCAN_T)
k_scan() {
    __shared__ int part[SCAN_T];
    int t = threadIdx.x;
    int base = t * SCAN_PER;
    int sum = 0;
#pragma unroll 4
    for (int i = 0; i < SCAN_PER; i++) {
        int idx = base + i;
        if (idx < N_NODES) sum += g_deg[idx];
    }
    part[t] = sum;
    __syncthreads();
    for (int o = 1; o < SCAN_T; o <<= 1) {
        int v = (t >= o) ? part[t - o] : 0;
        __syncthreads();
        part[t] += v;
        __syncthreads();
    }
    int off = (t == 0) ? 0 : part[t - 1];
    for (int i = 0; i < SCAN_PER; i++) {
        int idx = base + i;
        if (idx < N_NODES) {
            g_off[idx] = off;
            g_cursor[idx] = off;
            off += g_deg[idx];
        }
    }
    if (t == SCAN_T - 1) g_off[N_NODES] = off;
}

__global__ void k_fill(int E) {
    int e = blockIdx.x * blockDim.x + threadIdx.x;
    if (e >= E) return;
    int d = g_dst[e];
    int pos = atomicAdd(&g_cursor[d], 1);
    g_csr_src[pos] = g_src[e];
}

// ---------------------------------------------------------------------------
// TF32 helpers
// ---------------------------------------------------------------------------
__device__ __forceinline__ uint32_t f2tf32(float f) {
    uint32_t u;
    asm("cvt.rna.tf32.f32 %0, %1;" : "=r"(u) : "f"(f));
    return u;
}

__device__ __forceinline__ void mma_tf32(float* c, const uint32_t* a, const uint32_t* b) {
    asm volatile(
        "mma.sync.aligned.m16n8k8.row.col.f32.tf32.tf32.f32 "
        "{%0,%1,%2,%3}, {%4,%5,%6,%7}, {%8,%9}, {%0,%1,%2,%3};"
        : "+f"(c[0]), "+f"(c[1]), "+f"(c[2]), "+f"(c[3])
        : "r"(a[0]), "r"(a[1]), "r"(a[2]), "r"(a[3]),
          "r"(b[0]), "r"(b[1]));
}

// ---------------------------------------------------------------------------
// GEMM1 (TF32, cp.async double-buffered): h1 = X[40000,512] @ W1[512,256]
// Writes h1 in fp16 (feeds gather aggregation).
// Block 128x128, 256 threads, 8 warps (4x2), warp tile 32x64, BK=16.
// ---------------------------------------------------------------------------
#define BK1 16
#define NKT (DIN / BK1)   // 32
__global__ void __launch_bounds__(256, 2)
k_gemm1(const float* __restrict__ A,   // X
        const float* __restrict__ B) { // W1
    __shared__ float As[2][128][20];
    __shared__ float Bs[2][BK1][136];

    const int tid = threadIdx.x;
    const int warp = tid >> 5, lane = tid & 31;
    const int gid = lane >> 2, tig = lane & 3;
    const int warpRow = warp >> 1, warpCol = warp & 1;
    const int bm = blockIdx.y * 128;
    const int bn = blockIdx.x * 128;

    const int a_r0 = tid >> 2,           a_c0 = (tid & 3) * 4;
    const int a_r1 = (tid + 256) >> 2,   a_c1 = a_c0;
    const int a_g0 = (bm + a_r0 < N_NODES) ? bm + a_r0 : N_NODES - 1;
    const int a_g1 = (bm + a_r1 < N_NODES) ? bm + a_r1 : N_NODES - 1;
    const int b_r0 = tid >> 5,           b_c0 = (tid & 31) * 4;
    const int b_r1 = (tid + 256) >> 5,   b_c1 = b_c0;

    float acc[2][8][4];
#pragma unroll
    for (int mi = 0; mi < 2; mi++)
#pragma unroll
        for (int ni = 0; ni < 8; ni++)
#pragma unroll
            for (int r = 0; r < 4; r++) acc[mi][ni][r] = 0.0f;

    {
        cp16(&As[0][a_r0][a_c0], &A[(size_t)a_g0 * DIN + a_c0]);
        cp16(&As[0][a_r1][a_c1], &A[(size_t)a_g1 * DIN + a_c1]);
        cp16(&Bs[0][b_r0][b_c0], &B[(size_t)b_r0 * DH + bn + b_c0]);
        cp16(&Bs[0][b_r1][b_c1], &B[(size_t)b_r1 * DH + bn + b_c1]);
        asm volatile("cp.async.commit_group;");
    }

    int buf = 0;
    for (int kt = 0; kt < NKT; kt++) {
        if (kt + 1 < NKT) {
            int k0 = (kt + 1) * BK1;
            int nb = buf ^ 1;
            cp16(&As[nb][a_r0][a_c0], &A[(size_t)a_g0 * DIN + k0 + a_c0]);
            cp16(&As[nb][a_r1][a_c1], &A[(size_t)a_g1 * DIN + k0 + a_c1]);
            cp16(&Bs[nb][b_r0][b_c0], &B[(size_t)(k0 + b_r0) * DH + bn + b_c0]);
            cp16(&Bs[nb][b_r1][b_c1], &B[(size_t)(k0 + b_r1) * DH + bn + b_c1]);
            asm volatile("cp.async.commit_group;");
            asm volatile("cp.async.wait_group 1;");
        } else {
            asm volatile("cp.async.wait_group 0;");
        }
        __syncthreads();

#pragma unroll
        for (int kk = 0; kk < 2; kk++) {
            int kc = kk * 8 + tig;
            uint32_t a[2][4], b[8][2];
#pragma unroll
            for (int mi = 0; mi < 2; mi++) {
                int r = warpRow * 32 + mi * 16 + gid;
                a[mi][0] = f2tf32(As[buf][r][kc]);
                a[mi][1] = f2tf32(As[buf][r + 8][kc]);
                a[mi][2] = f2tf32(As[buf][r][kc + 4]);
                a[mi][3] = f2tf32(As[buf][r + 8][kc + 4]);
            }
#pragma unroll
            for (int ni = 0; ni < 8; ni++) {
                int c = warpCol * 64 + ni * 8 + gid;
                b[ni][0] = f2tf32(Bs[buf][kc][c]);
                b[ni][1] = f2tf32(Bs[buf][kc + 4][c]);
            }
#pragma unroll
            for (int mi = 0; mi < 2; mi++)
#pragma unroll
                for (int ni = 0; ni < 8; ni++)
                    mma_tf32(acc[mi][ni], a[mi], b[ni]);
        }
        __syncthreads();
        buf ^= 1;
    }

#pragma unroll
    for (int mi = 0; mi < 2; mi++) {
        int row0 = bm + warpRow * 32 + mi * 16 + gid;
        int row1 = row0 + 8;
#pragma unroll
        for (int ni = 0; ni < 8; ni++) {
            int col = bn + warpCol * 64 + ni * 8 + tig * 2;
            if (row0 < N_NODES)
                *reinterpret_cast<__half2*>(&g_h1h[(size_t)row0 * DH + col]) =
                    __floats2half2_rn(acc[mi][ni][0], acc[mi][ni][1]);
            if (row1 < N_NODES)
                *reinterpret_cast<__half2*>(&g_h1h[(size_t)row1 * DH + col]) =
                    __floats2half2_rn(acc[mi][ni][2], acc[mi][ni][3]);
        }
    }
}

// ---------------------------------------------------------------------------
// Layer-1 gather aggregation: o1[d] = b1 + dis[d]^2*h1[d] + sum_s nrm*h1[s]
// Block (64,4): 4 nodes per block, 64 lanes = 4-feature chunks of 256.
// fp16 gather (8B per lane per row), fp32 accumulate, x2 unrolled for MLP.
// ---------------------------------------------------------------------------
__global__ void __launch_bounds__(256)
k_agg1g(const float* __restrict__ b1) {
    int d = blockIdx.x * 4 + threadIdx.y;
    int c = threadIdx.x;
    float dd = g_dis[d];
    float w = dd * dd;

    float4 bb = reinterpret_cast<const float4*>(b1)[c];
    float2 slo, shi;
    ldh4(&g_h1h[(size_t)d * DH + c * 4], slo, shi);
    float4 acc = make_float4(bb.x + w * slo.x, bb.y + w * slo.y,
                             bb.z + w * shi.x, bb.w + w * shi.y);

    int i = g_off[d], end = g_off[d + 1];
    for (; i + 1 < end; i += 2) {
        int s0 = g_csr_src[i];
        int s1 = g_csr_src[i + 1];
        float n0 = g_dis[s0] * dd;
        float n1 = g_dis[s1] * dd;
        float2 a0, a1, b0, b_1;
        ldh4(&g_h1h[(size_t)s0 * DH + c * 4], a0, a1);
        ldh4(&g_h1h[(size_t)s1 * DH + c * 4], b0, b_1);
        acc.x += n0 * a0.x + n1 * b0.x;
        acc.y += n0 * a0.y + n1 * b0.y;
        acc.z += n0 * a1.x + n1 * b_1.x;
        acc.w += n0 * a1.y + n1 * b_1.y;
    }
    if (i < end) {
        int s = g_csr_src[i];
        float nrm = g_dis[s] * dd;
        float2 v0, v1;
        ldh4(&g_h1h[(size_t)s * DH + c * 4], v0, v1);
        acc.x += nrm * v0.x; acc.y += nrm * v0.y;
        acc.z += nrm * v1.x; acc.w += nrm * v1.y;
    }
    *reinterpret_cast<float4*>(&g_o1[(size_t)d * DH + c * 4]) = acc;
}

// ---------------------------------------------------------------------------
// GEMM2: h2 = relu(o1)[40000,256] @ W2[256,47] into padded stride-48 fp16,
// fused relu on load. Pad col = 0.
// ---------------------------------------------------------------------------
__global__ void __launch_bounds__(256)
k_gemm2(const float* __restrict__ W2) {
    __shared__ float hrow[4][DH];
    int row = blockIdx.x * 4 + threadIdx.y;

    for (int k = threadIdx.x; k < DH; k += 64)
        hrow[threadIdx.y][k] = fmaxf(g_o1[(size_t)row * DH + k], 0.0f);
    __syncthreads();

    int col = threadIdx.x;
    if (col < DOUT) {
        float acc = 0.0f;
#pragma unroll 8
        for (int k = 0; k < DH; k++)
            acc += hrow[threadIdx.y][k] * W2[k * DOUT + col];
        g_h2h[(size_t)row * DP + col] = __float2half_rn(acc);
    } else if (col == DOUT) {
        g_h2h[(size_t)row * DP + DOUT] = __float2half_rn(0.0f);
    }
}

// ---------------------------------------------------------------------------
// Layer-2 gather aggregation FUSED with log-softmax.
// Block (16,16): 16 nodes per block; 16 lanes per node (12 active 4-feature
// chunks of the padded 48-wide fp16 row). Reductions via width-16 shuffles.
// ---------------------------------------------------------------------------
__global__ void __launch_bounds__(256)
k_agg2g(const float* __restrict__ b2, float* __restrict__ out) {
    int d = blockIdx.x * 16 + threadIdx.y;
    int c = threadIdx.x;          // 0..15; chunks 12..15 inactive
    float dd = g_dis[d];

    float4 acc = make_float4(-INFINITY, -INFINITY, -INFINITY, -INFINITY);
    int col = c * 4;
    if (c < 12) {
        float w = dd * dd;
        float4 bb;
        bb.x = b2[col];
        bb.y = b2[col + 1];
        bb.z = b2[col + 2];
        bb.w = (col + 3 < DOUT) ? b2[col + 3] : 0.0f;
        float2 slo, shi;
        ldh4(&g_h2h[(size_t)d * DP + col], slo, shi);
        acc = make_float4(bb.x + w * slo.x, bb.y + w * slo.y,
                          bb.z + w * shi.x, bb.w + w * shi.y);
        int i = g_off[d], end = g_off[d + 1];
        for (; i + 1 < end; i += 2) {
            int s0 = g_csr_src[i];
            int s1 = g_csr_src[i + 1];
            float n0 = g_dis[s0] * dd;
            float n1 = g_dis[s1] * dd;
            float2 a0, a1, b0, b_1;
            ldh4(&g_h2h[(size_t)s0 * DP + col], a0, a1);
            ldh4(&g_h2h[(size_t)s1 * DP + col], b0, b_1);
            acc.x += n0 * a0.x + n1 * b0.x;
            acc.y += n0 * a0.y + n1 * b0.y;
            acc.z += n0 * a1.x + n1 * b_1.x;
            acc.w += n0 * a1.y + n1 * b_1.y;
        }
        if (i < end) {
            int s = g_csr_src[i];
            float nrm = g_dis[s] * dd;
            float2 v0, v1;
            ldh4(&g_h2h[(size_t)s * DP + col], v0, v1);
            acc.x += nrm * v0.x; acc.y += nrm * v0.y;
            acc.z += nrm * v1.x; acc.w += nrm * v1.y;
        }
        if (col + 3 >= DOUT) acc.w = -INFINITY;   // pad column
    }

    // log-softmax across the 16-lane group (47 valid values).
    float m = fmaxf(fmaxf(acc.x, acc.y), fmaxf(acc.z, acc.w));
#pragma unroll
    for (int o = 8; o; o >>= 1) m = fmaxf(m, __shfl_xor_sync(0xFFFFFFFFu, m, o, 16));
    float s = __expf(acc.x - m) + __expf(acc.y - m) +
              __expf(acc.z - m) + __expf(acc.w - m);   // exp(-inf)=0
#pragma unroll
    for (int o = 8; o; o >>= 1) s += __shfl_xor_sync(0xFFFFFFFFu, s, o, 16);
    float lg = m + logf(s);

    if (c < 12) {
        float* po = &out[(size_t)d * DOUT + col];
        po[0] = acc.x - lg;
        po[1] = acc.y - lg;
        po[2] = acc.z - lg;
        if (col + 3 < DOUT) po[3] = acc.w - lg;
    }
}

// ---------------------------------------------------------------------------
extern "C" void kernel_launch(void* const* d_in, const int* in_sizes, int n_in,
                              void* d_out, int out_size) {
    const float* x  = (const float*)d_in[0];
    const int*   ew = (const int*)d_in[1];    // edge_index words (int32 view)
    const float* W1 = (const float*)d_in[2];
    const float* b1 = (const float*)d_in[3];
    const float* W2 = (const float*)d_in[4];
    const float* b2 = (const float*)d_in[5];
    float* out = (float*)d_out;
    const int E = in_sizes[1] / 2;

    k_detect_init<<<1, 1>>>();
    k_detect<<<(E + 255) / 256, 256>>>(ew, 2 * E);
    k_extract<<<(E + 255) / 256, 256>>>(ew, E);

    k_zero_deg<<<(N_NODES + 255) / 256, 256>>>();
    k_count_deg<<<(E + 255) / 256, 256>>>(E);
    k_dis<<<(N_NODES + 255) / 256, 256>>>();
    k_scan<<<1, SCAN_T>>>();
    k_fill<<<(E + 255) / 256, 256>>>(E);

    dim3 g1(DH / 128, (N_NODES + 127) / 128);
    k_gemm1<<<g1, 256>>>(x, W1);

    k_agg1g<<<N_NODES / 4, dim3(64, 4)>>>(b1);

    k_gemm2<<<N_NODES / 4, dim3(64, 4)>>>(W2);

    k_agg2g<<<N_NODES / 16, dim3(16, 16)>>>(b2, out);
}

// round 11
// speedup vs baseline: 2.7886x; 1.0463x over previous
#include <cuda_runtime.h>
#include <cuda_fp16.h>
#include <cstdint>
#include <math.h>

#define N_NODES 40000
#define DIN 512
#define DH 256
#define DOUT 47
#define DP 48            // padded layer-2 width (multiple of 4)
#define MAX_E 640000

// Scratch (no cudaMalloc allowed) — __device__ globals.
__device__ __align__(16) __half g_xh[N_NODES * DIN]; // X in fp16
__device__ __align__(16) __half g_w1t[DH * DIN];     // W1^T in fp16 [n][k]
__device__ __align__(16) __half g_h1h[N_NODES * DH]; // X @ W1 (fp16 storage)
__device__ __align__(16) float  g_o1[N_NODES * DH];  // aggregated layer-1 (pre-relu)
__device__ __align__(16) __half g_h2h[N_NODES * DP]; // relu(o1) @ W2 (fp16, padded)
__device__ float g_dis[N_NODES];                     // deg^-1/2 (deg includes self-loop)
__device__ int   g_deg[N_NODES];
__device__ int   g_src[MAX_E];
__device__ int   g_dst[MAX_E];
__device__ int   g_off[N_NODES + 1];                 // CSR row offsets (by dst)
__device__ int   g_cursor[N_NODES];                  // fill cursors
__device__ int   g_csr_src[MAX_E];                   // src indices sorted by dst
__device__ int   g_is64;                             // 1 if edge_index is int64

__device__ __forceinline__ void cp16(void* smem_dst, const void* gsrc) {
    uint32_t s = (uint32_t)__cvta_generic_to_shared(smem_dst);
    asm volatile("cp.async.cg.shared.global [%0], [%1], 16;" :: "r"(s), "l"(gsrc));
}

// Load 4 consecutive halfs as 2 float2.
__device__ __forceinline__ void ldh4(const __half* p, float2& lo, float2& hi) {
    uint2 u = *reinterpret_cast<const uint2*>(p);
    lo = __half22float2(*reinterpret_cast<const __half2*>(&u.x));
    hi = __half22float2(*reinterpret_cast<const __half2*>(&u.y));
}

// ---------------------------------------------------------------------------
// Dtype detection (int32 vs int64 edge_index), index normalization.
// ---------------------------------------------------------------------------
__global__ void k_detect_init() { g_is64 = 1; }

__global__ void k_detect(const int* __restrict__ w, int nwords2E) {
    int i = blockIdx.x * blockDim.x + threadIdx.x;
    int odd = 2 * i + 1;
    if (odd < nwords2E && w[odd] != 0) g_is64 = 0;
}

__global__ void k_extract(const int* __restrict__ w, int E) {
    int e = blockIdx.x * blockDim.x + threadIdx.x;
    if (e >= E) return;
    if (g_is64) {
        g_src[e] = w[2 * e];
        g_dst[e] = w[2 * (E + e)];
    } else {
        g_src[e] = w[e];
        g_dst[e] = w[E + e];
    }
}

// ---------------------------------------------------------------------------
// Input conversions to fp16.
// ---------------------------------------------------------------------------
__global__ void __launch_bounds__(256)
k_convX(const float* __restrict__ x) {
    size_t i = ((size_t)blockIdx.x * 256 + threadIdx.x) * 8;
    float4 v0 = *reinterpret_cast<const float4*>(&x[i]);
    float4 v1 = *reinterpret_cast<const float4*>(&x[i + 4]);
    __half2 h[4];
    h[0] = __floats2half2_rn(v0.x, v0.y);
    h[1] = __floats2half2_rn(v0.z, v0.w);
    h[2] = __floats2half2_rn(v1.x, v1.y);
    h[3] = __floats2half2_rn(v1.z, v1.w);
    *reinterpret_cast<uint4*>(&g_xh[i]) = *reinterpret_cast<uint4*>(h);
}

__global__ void __launch_bounds__(256)
k_convW1t(const float* __restrict__ W1) {
    int idx = blockIdx.x * 256 + threadIdx.x;   // over DH*DIN
    if (idx >= DH * DIN) return;
    int n = idx / DIN, k = idx % DIN;
    g_w1t[idx] = __float2half_rn(W1[(size_t)k * DH + n]);
}

// ---------------------------------------------------------------------------
// Degree / normalization / CSR build
// ---------------------------------------------------------------------------
__global__ void k_zero_deg() {
    int i = blockIdx.x * blockDim.x + threadIdx.x;
    if (i < N_NODES) g_deg[i] = 0;
}

__global__ void k_count_deg(int E) {
    int i = blockIdx.x * blockDim.x + threadIdx.x;
    if (i < E) atomicAdd(&g_deg[g_dst[i]], 1);
}

__global__ void k_dis() {
    int i = blockIdx.x * blockDim.x + threadIdx.x;
    if (i < N_NODES) g_dis[i] = rsqrtf((float)g_deg[i] + 1.0f);  // +1 = self loop
}

// Single-block exclusive prefix scan over g_deg -> g_off, init cursors.
#define SCAN_T 1024
#define SCAN_PER ((N_NODES + SCAN_T - 1) / SCAN_T)   // 40
__global__ void __launch_bounds__(SCAN_T)
k_scan() {
    __shared__ int part[SCAN_T];
    int t = threadIdx.x;
    int base = t * SCAN_PER;
    int sum = 0;
#pragma unroll 4
    for (int i = 0; i < SCAN_PER; i++) {
        int idx = base + i;
        if (idx < N_NODES) sum += g_deg[idx];
    }
    part[t] = sum;
    __syncthreads();
    for (int o = 1; o < SCAN_T; o <<= 1) {
        int v = (t >= o) ? part[t - o] : 0;
        __syncthreads();
        part[t] += v;
        __syncthreads();
    }
    int off = (t == 0) ? 0 : part[t - 1];
    for (int i = 0; i < SCAN_PER; i++) {
        int idx = base + i;
        if (idx < N_NODES) {
            g_off[idx] = off;
            g_cursor[idx] = off;
            off += g_deg[idx];
        }
    }
    if (t == SCAN_T - 1) g_off[N_NODES] = off;
}

__global__ void k_fill(int E) {
    int e = blockIdx.x * blockDim.x + threadIdx.x;
    if (e >= E) return;
    int d = g_dst[e];
    int pos = atomicAdd(&g_cursor[d], 1);
    g_csr_src[pos] = g_src[e];
}

// ---------------------------------------------------------------------------
// fp16 MMA m16n8k16
// ---------------------------------------------------------------------------
__device__ __forceinline__ void mma_f16(float* c, const uint32_t* a, const uint32_t* b) {
    asm volatile(
        "mma.sync.aligned.m16n8k16.row.col.f32.f16.f16.f32 "
        "{%0,%1,%2,%3}, {%4,%5,%6,%7}, {%8,%9}, {%0,%1,%2,%3};"
        : "+f"(c[0]), "+f"(c[1]), "+f"(c[2]), "+f"(c[3])
        : "r"(a[0]), "r"(a[1]), "r"(a[2]), "r"(a[3]),
          "r"(b[0]), "r"(b[1]));
}

// ---------------------------------------------------------------------------
// GEMM1 (fp16 tensor cores, cp.async double-buffered):
//   h1 = X[40000,512] @ W1[512,256], fp16 in / fp32 accum / fp16 out.
// Block 128x128, 256 threads, 8 warps (4x2), warp tile 32x64, BK=32.
// SMEM rows stride 40 halfs (80B): half2 fragment loads conflict-free
//   (bank = (20*row + tig) mod 32, distinct across the warp).
// A smem = X rows [128][k 32]; B smem = W1t rows (n) [128][k 32].
// ---------------------------------------------------------------------------
#define BKH 32
#define NKTH (DIN / BKH)   // 16
__global__ void __launch_bounds__(256, 2)
k_gemm1h() {
    __shared__ __half As[2][128][BKH + 8];
    __shared__ __half Bs[2][128][BKH + 8];

    const int tid = threadIdx.x;
    const int warp = tid >> 5, lane = tid & 31;
    const int gid = lane >> 2, tig = lane & 3;
    const int warpRow = warp >> 1, warpCol = warp & 1;
    const int bm = blockIdx.y * 128;
    const int bn = blockIdx.x * 128;

    // 128 rows x 32 halfs = 512 x 16B-chunks per tile; 2 per thread.
    const int r0 = tid >> 2,          c0 = (tid & 3) * 8;
    const int r1 = (tid + 256) >> 2,  c1 = c0;
    const int ag0 = (bm + r0 < N_NODES) ? bm + r0 : N_NODES - 1;
    const int ag1 = (bm + r1 < N_NODES) ? bm + r1 : N_NODES - 1;

    float acc[2][8][4];
#pragma unroll
    for (int mi = 0; mi < 2; mi++)
#pragma unroll
        for (int ni = 0; ni < 8; ni++)
#pragma unroll
            for (int r = 0; r < 4; r++) acc[mi][ni][r] = 0.0f;

    {
        cp16(&As[0][r0][c0], &g_xh[(size_t)ag0 * DIN + c0]);
        cp16(&As[0][r1][c1], &g_xh[(size_t)ag1 * DIN + c1]);
        cp16(&Bs[0][r0][c0], &g_w1t[(size_t)(bn + r0) * DIN + c0]);
        cp16(&Bs[0][r1][c1], &g_w1t[(size_t)(bn + r1) * DIN + c1]);
        asm volatile("cp.async.commit_group;");
    }

    int buf = 0;
    for (int kt = 0; kt < NKTH; kt++) {
        if (kt + 1 < NKTH) {
            int k0 = (kt + 1) * BKH;
            int nb = buf ^ 1;
            cp16(&As[nb][r0][c0], &g_xh[(size_t)ag0 * DIN + k0 + c0]);
            cp16(&As[nb][r1][c1], &g_xh[(size_t)ag1 * DIN + k0 + c1]);
            cp16(&Bs[nb][r0][c0], &g_w1t[(size_t)(bn + r0) * DIN + k0 + c0]);
            cp16(&Bs[nb][r1][c1], &g_w1t[(size_t)(bn + r1) * DIN + k0 + c1]);
            asm volatile("cp.async.commit_group;");
            asm volatile("cp.async.wait_group 1;");
        } else {
            asm volatile("cp.async.wait_group 0;");
        }
        __syncthreads();

#pragma unroll
        for (int kk = 0; kk < 2; kk++) {
            int kb = kk * 16 + tig * 2;
            uint32_t a[2][4], b[8][2];
#pragma unroll
            for (int mi = 0; mi < 2; mi++) {
                int r = warpRow * 32 + mi * 16 + gid;
                a[mi][0] = *reinterpret_cast<const uint32_t*>(&As[buf][r][kb]);
                a[mi][1] = *reinterpret_cast<const uint32_t*>(&As[buf][r + 8][kb]);
                a[mi][2] = *reinterpret_cast<const uint32_t*>(&As[buf][r][kb + 8]);
                a[mi][3] = *reinterpret_cast<const uint32_t*>(&As[buf][r + 8][kb + 8]);
            }
#pragma unroll
            for (int ni = 0; ni < 8; ni++) {
                int c = warpCol * 64 + ni * 8 + gid;
                b[ni][0] = *reinterpret_cast<const uint32_t*>(&Bs[buf][c][kb]);
                b[ni][1] = *reinterpret_cast<const uint32_t*>(&Bs[buf][c][kb + 8]);
            }
#pragma unroll
            for (int mi = 0; mi < 2; mi++)
#pragma unroll
                for (int ni = 0; ni < 8; ni++)
                    mma_f16(acc[mi][ni], a[mi], b[ni]);
        }
        __syncthreads();
        buf ^= 1;
    }

#pragma unroll
    for (int mi = 0; mi < 2; mi++) {
        int row0 = bm + warpRow * 32 + mi * 16 + gid;
        int row1 = row0 + 8;
#pragma unroll
        for (int ni = 0; ni < 8; ni++) {
            int col = bn + warpCol * 64 + ni * 8 + tig * 2;
            if (row0 < N_NODES)
                *reinterpret_cast<__half2*>(&g_h1h[(size_t)row0 * DH + col]) =
                    __floats2half2_rn(acc[mi][ni][0], acc[mi][ni][1]);
            if (row1 < N_NODES)
                *reinterpret_cast<__half2*>(&g_h1h[(size_t)row1 * DH + col]) =
                    __floats2half2_rn(acc[mi][ni][2], acc[mi][ni][3]);
        }
    }
}

// ---------------------------------------------------------------------------
// Layer-1 gather aggregation: o1[d] = b1 + dis[d]^2*h1[d] + sum_s nrm*h1[s]
// Block (64,4): 4 nodes per block, 64 lanes = 4-feature chunks of 256.
// fp16 gather, fp32 accumulate, x4 unrolled for MLP.
// ---------------------------------------------------------------------------
__global__ void __launch_bounds__(256)
k_agg1g(const float* __restrict__ b1) {
    int d = blockIdx.x * 4 + threadIdx.y;
    int c = threadIdx.x;
    float dd = g_dis[d];
    float w = dd * dd;

    float4 bb = reinterpret_cast<const float4*>(b1)[c];
    float2 slo, shi;
    ldh4(&g_h1h[(size_t)d * DH + c * 4], slo, shi);
    float4 acc = make_float4(bb.x + w * slo.x, bb.y + w * slo.y,
                             bb.z + w * shi.x, bb.w + w * shi.y);

    int i = g_off[d], end = g_off[d + 1];
    for (; i + 3 < end; i += 4) {
        int s0 = g_csr_src[i], s1 = g_csr_src[i + 1];
        int s2 = g_csr_src[i + 2], s3 = g_csr_src[i + 3];
        float n0 = g_dis[s0] * dd, n1 = g_dis[s1] * dd;
        float n2 = g_dis[s2] * dd, n3 = g_dis[s3] * dd;
        float2 a0, a1, b0, b1v, c0, c1, d0, d1;
        ldh4(&g_h1h[(size_t)s0 * DH + c * 4], a0, a1);
        ldh4(&g_h1h[(size_t)s1 * DH + c * 4], b0, b1v);
        ldh4(&g_h1h[(size_t)s2 * DH + c * 4], c0, c1);
        ldh4(&g_h1h[(size_t)s3 * DH + c * 4], d0, d1);
        acc.x += n0 * a0.x + n1 * b0.x + n2 * c0.x + n3 * d0.x;
        acc.y += n0 * a0.y + n1 * b0.y + n2 * c0.y + n3 * d0.y;
        acc.z += n0 * a1.x + n1 * b1v.x + n2 * c1.x + n3 * d1.x;
        acc.w += n0 * a1.y + n1 * b1v.y + n2 * c1.y + n3 * d1.y;
    }
    for (; i < end; i++) {
        int s = g_csr_src[i];
        float nrm = g_dis[s] * dd;
        float2 v0, v1;
        ldh4(&g_h1h[(size_t)s * DH + c * 4], v0, v1);
        acc.x += nrm * v0.x; acc.y += nrm * v0.y;
        acc.z += nrm * v1.x; acc.w += nrm * v1.y;
    }
    *reinterpret_cast<float4*>(&g_o1[(size_t)d * DH + c * 4]) = acc;
}

// ---------------------------------------------------------------------------
// GEMM2: h2 = relu(o1)[40000,256] @ W2[256,47] into padded stride-48 fp16,
// fused relu on load. Pad col = 0.
// ---------------------------------------------------------------------------
__global__ void __launch_bounds__(256)
k_gemm2(const float* __restrict__ W2) {
    __shared__ float hrow[4][DH];
    int row = blockIdx.x * 4 + threadIdx.y;

    for (int k = threadIdx.x; k < DH; k += 64)
        hrow[threadIdx.y][k] = fmaxf(g_o1[(size_t)row * DH + k], 0.0f);
    __syncthreads();

    int col = threadIdx.x;
    if (col < DOUT) {
        float acc = 0.0f;
#pragma unroll 8
        for (int k = 0; k < DH; k++)
            acc += hrow[threadIdx.y][k] * W2[k * DOUT + col];
        g_h2h[(size_t)row * DP + col] = __float2half_rn(acc);
    } else if (col == DOUT) {
        g_h2h[(size_t)row * DP + DOUT] = __float2half_rn(0.0f);
    }
}

// ---------------------------------------------------------------------------
// Layer-2 gather aggregation FUSED with log-softmax.
// Block (16,16): 16 nodes per block; 16 lanes per node (12 active 4-feature
// chunks of the padded 48-wide fp16 row). Reductions via width-16 shuffles.
// ---------------------------------------------------------------------------
__global__ void __launch_bounds__(256)
k_agg2g(const float* __restrict__ b2, float* __restrict__ out) {
    int d = blockIdx.x * 16 + threadIdx.y;
    int c = threadIdx.x;          // 0..15; chunks 12..15 inactive
    float dd = g_dis[d];

    float4 acc = make_float4(-INFINITY, -INFINITY, -INFINITY, -INFINITY);
    int col = c * 4;
    if (c < 12) {
        float w = dd * dd;
        float4 bb;
        bb.x = b2[col];
        bb.y = b2[col + 1];
        bb.z = b2[col + 2];
        bb.w = (col + 3 < DOUT) ? b2[col + 3] : 0.0f;
        float2 slo, shi;
        ldh4(&g_h2h[(size_t)d * DP + col], slo, shi);
        acc = make_float4(bb.x + w * slo.x, bb.y + w * slo.y,
                          bb.z + w * shi.x, bb.w + w * shi.y);
        int i = g_off[d], end = g_off[d + 1];
        for (; i + 1 < end; i += 2) {
            int s0 = g_csr_src[i];
            int s1 = g_csr_src[i + 1];
            float n0 = g_dis[s0] * dd;
            float n1 = g_dis[s1] * dd;
            float2 a0, a1, b0, b_1;
            ldh4(&g_h2h[(size_t)s0 * DP + col], a0, a1);
            ldh4(&g_h2h[(size_t)s1 * DP + col], b0, b_1);
            acc.x += n0 * a0.x + n1 * b0.x;
            acc.y += n0 * a0.y + n1 * b0.y;
            acc.z += n0 * a1.x + n1 * b_1.x;
            acc.w += n0 * a1.y + n1 * b_1.y;
        }
        if (i < end) {
            int s = g_csr_src[i];
            float nrm = g_dis[s] * dd;
            float2 v0, v1;
            ldh4(&g_h2h[(size_t)s * DP + col], v0, v1);
            acc.x += nrm * v0.x; acc.y += nrm * v0.y;
            acc.z += nrm * v1.x; acc.w += nrm * v1.y;
        }
        if (col + 3 >= DOUT) acc.w = -INFINITY;   // pad column
    }

    // log-softmax across the 16-lane group (47 valid values).
    float m = fmaxf(fmaxf(acc.x, acc.y), fmaxf(acc.z, acc.w));
#pragma unroll
    for (int o = 8; o; o >>= 1) m = fmaxf(m, __shfl_xor_sync(0xFFFFFFFFu, m, o, 16));
    float s = __expf(acc.x - m) + __expf(acc.y - m) +
              __expf(acc.z - m) + __expf(acc.w - m);   // exp(-inf)=0
#pragma unroll
    for (int o = 8; o; o >>= 1) s += __shfl_xor_sync(0xFFFFFFFFu, s, o, 16);
    float lg = m + logf(s);

    if (c < 12) {
        float* po = &out[(size_t)d * DOUT + col];
        po[0] = acc.x - lg;
        po[1] = acc.y - lg;
        po[2] = acc.z - lg;
        if (col + 3 < DOUT) po[3] = acc.w - lg;
    }
}

// ---------------------------------------------------------------------------
extern "C" void kernel_launch(void* const* d_in, const int* in_sizes, int n_in,
                              void* d_out, int out_size) {
    const float* x  = (const float*)d_in[0];
    const int*   ew = (const int*)d_in[1];    // edge_index words (int32 view)
    const float* W1 = (const float*)d_in[2];
    const float* b1 = (const float*)d_in[3];
    const float* W2 = (const float*)d_in[4];
    const float* b2 = (const float*)d_in[5];
    float* out = (float*)d_out;
    const int E = in_sizes[1] / 2;

    k_detect_init<<<1, 1>>>();
    k_detect<<<(E + 255) / 256, 256>>>(ew, 2 * E);
    k_extract<<<(E + 255) / 256, 256>>>(ew, E);

    k_convX<<<(N_NODES * DIN / 8 + 255) / 256, 256>>>(x);
    k_convW1t<<<(DH * DIN + 255) / 256, 256>>>(W1);

    k_zero_deg<<<(N_NODES + 255) / 256, 256>>>();
    k_count_deg<<<(E + 255) / 256, 256>>>(E);
    k_dis<<<(N_NODES + 255) / 256, 256>>>();
    k_scan<<<1, SCAN_T>>>();
    k_fill<<<(E + 255) / 256, 256>>>(E);

    dim3 g1(DH / 128, (N_NODES + 127) / 128);
    k_gemm1h<<<g1, 256>>>();

    k_agg1g<<<N_NODES / 4, dim3(64, 4)>>>(b1);

    k_gemm2<<<N_NODES / 4, dim3(64, 4)>>>(W2);

    k_agg2g<<<N_NODES / 16, dim3(16, 16)>>>(b2, out);
}